// round 9
// baseline (speedup 1.0000x reference)
#include <cuda_runtime.h>
#include <cuda_bf16.h>
#include <math.h>

#define BD 512
#define MD 32768
#define NPREDD 20
#define FUTD 12
#define NROWS (BD*NPREDD)
#define NSLICE 76

// smem: 2 KV buffers only
// buf b at b*28160: Kh[64][56] bf16 (7168), Kl (7168), Vh[48][72] bf16 (6912), Vl (6912)
#define KVBUF_B   28160
#define SMEM_ATTN (2*KVBUF_B)

__device__ float g_state[BD*48];
__device__ float g_q[BD*48];
__device__ __nv_bfloat16 g_Kh[MD*48];
__device__ __nv_bfloat16 g_Kl[MD*48];
__device__ __nv_bfloat16 g_Vth[48*MD];
__device__ __nv_bfloat16 g_Vtl[48*MD];
__device__ float g_part[NSLICE*BD*52];
__device__ float g_pred[NROWS*48];
__device__ float g_wTih[96*288];
__device__ float g_wThh[96*288];

__device__ __forceinline__ float sg_(float x){ return 1.f/(1.f+__expf(-x)); }

__device__ __forceinline__ void cpa16(void* dst, const void* src){
    unsigned ds = (unsigned)__cvta_generic_to_shared(dst);
    asm volatile("cp.async.cg.shared.global [%0], [%1], 16;\n" :: "r"(ds), "l"(src));
}

#define MMA_BF16(c, a0,a1,a2,a3, b0,b1) \
    asm volatile("mma.sync.aligned.m16n8k16.row.col.f32.bf16.bf16.f32 " \
        "{%0,%1,%2,%3}, {%4,%5,%6,%7}, {%8,%9}, {%0,%1,%2,%3};" \
        : "+f"(c[0]), "+f"(c[1]), "+f"(c[2]), "+f"(c[3]) \
        : "r"(a0),"r"(a1),"r"(a2),"r"(a3),"r"(b0),"r"(b1))

__device__ __forceinline__ unsigned ldu32(const __nv_bfloat16* p){
    return *(const unsigned*)p;
}
__device__ __forceinline__ unsigned short us_(__nv_bfloat16 h){
    return *(unsigned short*)&h;
}
__device__ __forceinline__ void split2(float a, float b, unsigned &hi, unsigned &lo){
    __nv_bfloat16 ha = __float2bfloat16(a), hb = __float2bfloat16(b);
    __nv_bfloat16 la = __float2bfloat16(a - __bfloat162float(ha));
    __nv_bfloat16 lb = __float2bfloat16(b - __bfloat162float(hb));
    hi = (unsigned)us_(ha) | ((unsigned)us_(hb) << 16);
    lo = (unsigned)us_(la) | ((unsigned)us_(lb) << 16);
}

// ---------- encoder ----------
__global__ void enc_kernel(const float* __restrict__ past,
    const float* __restrict__ cw, const float* __restrict__ cb,
    const float* __restrict__ wih, const float* __restrict__ whh,
    const float* __restrict__ bih, const float* __restrict__ bhh,
    const float* __restrict__ Wq, const float* __restrict__ bq)
{
    __shared__ float se[8][48];
    __shared__ float sh[48];
    __shared__ float sgi[144], sgh[144];
    int b = blockIdx.x, tid = threadIdx.x;
    for (int idx = tid; idx < 8*48; idx += 144) {
        int t = idx/48, c = idx%48;
        float s = cb[c];
        #pragma unroll
        for (int k = 0; k < 3; k++) {
            int tt = t + k - 1;
            if (tt >= 0 && tt < 8) {
                s = fmaf(cw[c*6+k],   past[b*16+tt*2+0], s);
                s = fmaf(cw[c*6+3+k], past[b*16+tt*2+1], s);
            }
        }
        se[t][c] = fmaxf(s, 0.f);
    }
    if (tid < 48) sh[tid] = 0.f;
    __syncthreads();
    for (int t = 0; t < 8; t++) {
        float gi = bih[tid], gh = bhh[tid];
        const float* wi = wih + tid*48;
        const float* wh = whh + tid*48;
        #pragma unroll 8
        for (int d = 0; d < 48; d++) {
            gi = fmaf(se[t][d], wi[d], gi);
            gh = fmaf(sh[d],    wh[d], gh);
        }
        sgi[tid] = gi; sgh[tid] = gh;
        __syncthreads();
        float hn = 0.f;
        if (tid < 48) {
            float r = sg_(sgi[tid]    + sgh[tid]);
            float z = sg_(sgi[48+tid] + sgh[48+tid]);
            float n = tanhf(sgi[96+tid] + r*sgh[96+tid]);
            hn = (1.f-z)*n + z*sh[tid];
        }
        __syncthreads();
        if (tid < 48) sh[tid] = hn;
        __syncthreads();
    }
    if (tid < 48) {
        g_state[b*48+tid] = sh[tid];
        float q = bq[tid];
        const float* w = Wq + tid*48;
        #pragma unroll 8
        for (int d = 0; d < 48; d++) q = fmaf(sh[d], w[d], q);
        g_q[b*48+tid] = q;
    }
}

// ---------- K projection + hi/lo split (m-major) ----------
__global__ void kproj_kernel(const float* __restrict__ mp,
    const float* __restrict__ Wk, const float* __restrict__ bk)
{
    int idx = blockIdx.x*blockDim.x + threadIdx.x;
    if (idx >= MD*48) return;
    int m = idx/48, j = idx - m*48;
    const float* rp = mp + m*48;
    const float* wk = Wk + j*48;
    float sk = bk[j];
    #pragma unroll 8
    for (int d = 0; d < 48; d++) sk = fmaf(rp[d], wk[d], sk);
    __nv_bfloat16 h = __float2bfloat16(sk);
    g_Kh[idx] = h;
    g_Kl[idx] = __float2bfloat16(sk - __bfloat162float(h));
}

// ---------- V projection + hi/lo split, transposed (d-major) ----------
__global__ void vproj_kernel(const float* __restrict__ mf,
    const float* __restrict__ Wv, const float* __restrict__ bv)
{
    __shared__ float sW[48*48];
    __shared__ float sb[48];
    int tid = threadIdx.x;
    for (int i = tid; i < 48*48; i += 256) sW[i] = Wv[i];
    if (tid < 48) sb[tid] = bv[tid];
    __syncthreads();
    int m = blockIdx.x*256 + tid;
    float r[48];
    #pragma unroll 8
    for (int d = 0; d < 48; d++) r[d] = mf[(size_t)m*48 + d];
    #pragma unroll 1
    for (int j = 0; j < 48; j++) {
        float sv = sb[j];
        const float* w = sW + j*48;
        #pragma unroll 8
        for (int d = 0; d < 48; d++) sv = fmaf(r[d], w[d], sv);
        __nv_bfloat16 h = __float2bfloat16(sv);
        g_Vth[(size_t)j*MD + m] = h;
        g_Vtl[(size_t)j*MD + m] = __float2bfloat16(sv - __bfloat162float(h));
    }
}

// ---------- decoder weight transpose ----------
__global__ void wt_kernel(const float* __restrict__ wih, const float* __restrict__ whh)
{
    int i = blockIdx.x*blockDim.x + threadIdx.x;
    if (i < 288*96) {
        int j = i/96, k = i - j*96;
        g_wTih[k*288+j] = wih[i];
        g_wThh[k*288+j] = whh[i];
    }
}

// ---------- prefetch helper ----------
__device__ __forceinline__ void prefetch_chunk(char* base, int m0, int tid){
    #pragma unroll
    for (int i = tid; i < 768; i += 128) {
        int arr = i / 384;
        int r = (i % 384) / 6, seg = i % 6;
        const char* src = (const char*)(arr ? g_Kl : g_Kh) + ((size_t)(m0+r)*48)*2 + seg*16;
        cpa16(base + arr*7168 + r*112 + seg*16, src);
    }
    #pragma unroll
    for (int i = tid; i < 768; i += 128) {
        int arr = i / 384;
        int r = (i % 384) / 8, seg = i % 8;
        const char* src = (const char*)(arr ? g_Vtl : g_Vth) + ((size_t)r*MD + m0)*2 + seg*16;
        cpa16(base + 14336 + arr*6912 + r*144 + seg*16, src);
    }
}

// ---------- attention: register-resident FA2, bf16-split HMMA, 4 CTA/SM ----------
__global__ void __launch_bounds__(128,4) attn_kernel()
{
    extern __shared__ char sm[];
    int tid = threadIdx.x, lane = tid & 31, w = tid >> 5;
    int gid = lane >> 2, tg = lane & 3;
    int qbase = blockIdx.y * 64;
    int s = blockIdx.x;
    int m_start = (s < 56) ? s*448 : 25088 + (s-56)*384;
    int nch = (s < 56) ? 7 : 6;

    // q fragments straight from gmem (row-major [q][48])
    unsigned qh[3][4], ql[3][4];
    {
        int r0 = qbase + w*16 + gid, r1 = r0 + 8;
        const float* Q0 = g_q + (size_t)r0*48;
        const float* Q1 = g_q + (size_t)r1*48;
        #pragma unroll
        for (int j = 0; j < 3; j++) {
            int c = j*16 + tg*2;
            split2(Q0[c],   Q0[c+1], qh[j][0], ql[j][0]);
            split2(Q1[c],   Q1[c+1], qh[j][1], ql[j][1]);
            split2(Q0[c+8], Q0[c+9], qh[j][2], ql[j][2]);
            split2(Q1[c+8], Q1[c+9], qh[j][3], ql[j][3]);
        }
    }

    prefetch_chunk(sm, m_start, tid);
    asm volatile("cp.async.commit_group;\n");

    float O[6][4];
    #pragma unroll
    for (int dt = 0; dt < 6; dt++) { O[dt][0]=0.f; O[dt][1]=0.f; O[dt][2]=0.f; O[dt][3]=0.f; }
    float rm0 = -1e30f, rm1 = -1e30f, rs0 = 0.f, rs1 = 0.f;

    for (int c = 0; c < nch; c++) {
        asm volatile("cp.async.wait_group 0;\n" ::: "memory");
        __syncthreads();
        if (c + 1 < nch)
            prefetch_chunk(sm + ((c+1)&1)*KVBUF_B, m_start + (c+1)*64, tid);
        asm volatile("cp.async.commit_group;\n");

        const __nv_bfloat16* Kh = (const __nv_bfloat16*)(sm + (c&1)*KVBUF_B);
        const __nv_bfloat16* Kl = Kh + 64*56;
        const __nv_bfloat16* Vh = (const __nv_bfloat16*)(sm + (c&1)*KVBUF_B + 14336);
        const __nv_bfloat16* Vl = Vh + 48*72;

        // ---- QK^T: warp computes full 16q x 64m ----
        float Sc[8][4];
        #pragma unroll
        for (int nt = 0; nt < 8; nt++) { Sc[nt][0]=0.f; Sc[nt][1]=0.f; Sc[nt][2]=0.f; Sc[nt][3]=0.f; }
        #pragma unroll
        for (int j = 0; j < 3; j++) {
            int kc = j*16 + tg*2;
            #pragma unroll
            for (int nt = 0; nt < 8; nt++) {
                const __nv_bfloat16* kr = Kh + (nt*8+gid)*56 + kc;
                const __nv_bfloat16* lr = Kl + (nt*8+gid)*56 + kc;
                unsigned kh0 = ldu32(kr), kh1 = ldu32(kr + 8);
                unsigned kl0 = ldu32(lr), kl1 = ldu32(lr + 8);
                MMA_BF16(Sc[nt], qh[j][0],qh[j][1],qh[j][2],qh[j][3], kh0,kh1);
                MMA_BF16(Sc[nt], qh[j][0],qh[j][1],qh[j][2],qh[j][3], kl0,kl1);
                MMA_BF16(Sc[nt], ql[j][0],ql[j][1],ql[j][2],ql[j][3], kh0,kh1);
            }
        }

        // ---- in-register online softmax (row = 4 lanes of a quad) ----
        float m0 = Sc[0][0], m1 = Sc[0][2];
        #pragma unroll
        for (int nt = 0; nt < 8; nt++) {
            m0 = fmaxf(m0, fmaxf(Sc[nt][0], Sc[nt][1]));
            m1 = fmaxf(m1, fmaxf(Sc[nt][2], Sc[nt][3]));
        }
        m0 = fmaxf(m0, __shfl_xor_sync(0xffffffffu, m0, 1));
        m0 = fmaxf(m0, __shfl_xor_sync(0xffffffffu, m0, 2));
        m1 = fmaxf(m1, __shfl_xor_sync(0xffffffffu, m1, 1));
        m1 = fmaxf(m1, __shfl_xor_sync(0xffffffffu, m1, 2));
        float nm0 = fmaxf(rm0, m0), nm1 = fmaxf(rm1, m1);
        float f0 = __expf(rm0 - nm0), f1 = __expf(rm1 - nm1);
        rm0 = nm0; rm1 = nm1;
        rs0 *= f0; rs1 *= f1;
        #pragma unroll
        for (int dt = 0; dt < 6; dt++) {
            O[dt][0] *= f0; O[dt][1] *= f0;
            O[dt][2] *= f1; O[dt][3] *= f1;
        }

        // ---- exp + PV in two halves (shorter p live-range) ----
        #pragma unroll
        for (int half = 0; half < 2; half++) {
            unsigned p01h[4], p01l[4], p23h[4], p23l[4];
            #pragma unroll
            for (int k = 0; k < 4; k++) {
                int nt = half*4 + k;
                float p0 = __expf(Sc[nt][0] - nm0);
                float p1 = __expf(Sc[nt][1] - nm0);
                float p2 = __expf(Sc[nt][2] - nm1);
                float p3 = __expf(Sc[nt][3] - nm1);
                rs0 += p0 + p1; rs1 += p2 + p3;
                split2(p0, p1, p01h[k], p01l[k]);
                split2(p2, p3, p23h[k], p23l[k]);
            }
            #pragma unroll
            for (int tt = 0; tt < 2; tt++) {
                int t = half*2 + tt;
                unsigned ah0 = p01h[2*tt],   ah1 = p23h[2*tt];
                unsigned ah2 = p01h[2*tt+1], ah3 = p23h[2*tt+1];
                unsigned al0 = p01l[2*tt],   al1 = p23l[2*tt];
                unsigned al2 = p01l[2*tt+1], al3 = p23l[2*tt+1];
                int mk = t*16 + tg*2;
                #pragma unroll
                for (int dt = 0; dt < 6; dt++) {
                    const __nv_bfloat16* vr = Vh + (dt*8+gid)*72 + mk;
                    const __nv_bfloat16* wr = Vl + (dt*8+gid)*72 + mk;
                    unsigned vh0 = ldu32(vr), vh1 = ldu32(vr + 8);
                    unsigned vl0 = ldu32(wr), vl1 = ldu32(wr + 8);
                    MMA_BF16(O[dt], ah0,ah1,ah2,ah3, vh0,vh1);
                    MMA_BF16(O[dt], ah0,ah1,ah2,ah3, vl0,vl1);
                    MMA_BF16(O[dt], al0,al1,al2,al3, vh0,vh1);
                }
            }
        }
    }

    // ---- epilogue: finish row sums, write partials ----
    rs0 += __shfl_xor_sync(0xffffffffu, rs0, 1);
    rs0 += __shfl_xor_sync(0xffffffffu, rs0, 2);
    rs1 += __shfl_xor_sync(0xffffffffu, rs1, 1);
    rs1 += __shfl_xor_sync(0xffffffffu, rs1, 2);

    int gq0 = qbase + w*16 + gid, gq1 = gq0 + 8;
    float* P0 = g_part + ((size_t)s*BD + gq0)*52;
    float* P1 = g_part + ((size_t)s*BD + gq1)*52;
    #pragma unroll
    for (int dt = 0; dt < 6; dt++) {
        int col = dt*8 + tg*2;
        P0[col]   = O[dt][0];
        P0[col+1] = O[dt][1];
        P1[col]   = O[dt][2];
        P1[col+1] = O[dt][3];
    }
    if (tg == 0) {
        P0[48] = rm0; P0[49] = rs0;
        P1[48] = rm1; P1[49] = rs1;
    }
}

// ---------- combine partials + emit pred + next q (8 q per block) ----------
__global__ void combine_kernel(const float* __restrict__ Wq, const float* __restrict__ bq,
                               int iter)
{
    __shared__ float sc[8][48];
    int t = threadIdx.x;
    int ql = t / 48, d = t - ql*48;
    int q = blockIdx.x*8 + ql;
    float gm = -1e30f;
    #pragma unroll 4
    for (int s = 0; s < NSLICE; s++)
        gm = fmaxf(gm, g_part[((size_t)s*BD+q)*52 + 48]);
    float tot = 0.f, av = 0.f;
    #pragma unroll 4
    for (int s = 0; s < NSLICE; s++) {
        const float* P = g_part + ((size_t)s*BD+q)*52;
        float e = __expf(P[48] - gm);
        tot = fmaf(P[49], e, tot);
        av  = fmaf(P[d],  e, av);
    }
    float att = av / tot;
    g_pred[(q*NPREDD + iter)*48 + d] = att;
    sc[ql][d] = g_q[q*48+d] + att;
    __syncthreads();
    float qn = bq[d];
    const float* w = Wq + d*48;
    #pragma unroll 8
    for (int k = 0; k < 48; k++) qn = fmaf(sc[ql][k], w[k], qn);
    g_q[q*48+d] = qn;
}

// ---------- decoder: GRU(96) x 12, block = 16 rows, 288 threads ----------
__global__ void __launch_bounds__(288) dec_kernel(
    const float* __restrict__ obs,
    const float* __restrict__ bih, const float* __restrict__ bhh,
    const float* __restrict__ fcw, const float* __restrict__ fcb,
    float* __restrict__ out)
{
    __shared__ float xh[96*16];
    __shared__ float ghs[288*16];
    int tid = threadIdx.x;
    int nbase = blockIdx.x*16;

    for (int i = tid; i < 96*16; i += 288) {
        int k = i >> 4, r = i & 15;
        int n = nbase + r;
        xh[i] = (k < 48) ? g_state[(n/NPREDD)*48 + k] : g_pred[(size_t)n*48 + (k-48)];
    }
    float pres = 0.f;
    if (tid < 32) {
        int n = nbase + (tid >> 1);
        pres = obs[(n/NPREDD)*16 + 14 + (tid & 1)];
    }
    __syncthreads();

    for (int t = 0; t < FUTD; t++) {
        const float* W  = (t == 0) ? g_wTih : g_wThh;
        const float* b0 = (t == 0) ? bih : bhh;
        const float* b1 = (t == 0) ? bhh : bih;
        float acc[16];
        float bb = b0[tid];
        #pragma unroll
        for (int r = 0; r < 16; r++) acc[r] = bb;
        #pragma unroll 4
        for (int k = 0; k < 96; k++) {
            float wv = W[k*288 + tid];
            float4 a0 = *(const float4*)&xh[k*16 + 0];
            float4 a1 = *(const float4*)&xh[k*16 + 4];
            float4 a2 = *(const float4*)&xh[k*16 + 8];
            float4 a3 = *(const float4*)&xh[k*16 + 12];
            acc[0]=fmaf(a0.x,wv,acc[0]);  acc[1]=fmaf(a0.y,wv,acc[1]);
            acc[2]=fmaf(a0.z,wv,acc[2]);  acc[3]=fmaf(a0.w,wv,acc[3]);
            acc[4]=fmaf(a1.x,wv,acc[4]);  acc[5]=fmaf(a1.y,wv,acc[5]);
            acc[6]=fmaf(a1.z,wv,acc[6]);  acc[7]=fmaf(a1.w,wv,acc[7]);
            acc[8]=fmaf(a2.x,wv,acc[8]);  acc[9]=fmaf(a2.y,wv,acc[9]);
            acc[10]=fmaf(a2.z,wv,acc[10]); acc[11]=fmaf(a2.w,wv,acc[11]);
            acc[12]=fmaf(a3.x,wv,acc[12]); acc[13]=fmaf(a3.y,wv,acc[13]);
            acc[14]=fmaf(a3.z,wv,acc[14]); acc[15]=fmaf(a3.w,wv,acc[15]);
        }
        __syncthreads();
        #pragma unroll
        for (int r4 = 0; r4 < 4; r4++)
            *(float4*)&ghs[tid*16 + r4*4] =
                make_float4(acc[r4*4], acc[r4*4+1], acc[r4*4+2], acc[r4*4+3]);
        __syncthreads();

        for (int i = tid; i < 96*16; i += 288) {
            int d = i >> 4, r = i & 15;
            float gr = ghs[d*16 + r];
            float gz = ghs[(96+d)*16 + r];
            float gn = ghs[(192+d)*16 + r];
            float rg = sg_(gr + b1[d]);
            float z  = sg_(gz + b1[96+d]);
            float nn, h;
            if (t == 0) {
                nn = tanhf(gn + rg*b1[192+d]);
                h = (1.f - z)*nn;
            } else {
                nn = tanhf(b1[192+d] + rg*gn);
                h = (1.f - z)*nn + z*xh[d*16 + r];
            }
            xh[d*16 + r] = h;
        }
        __syncthreads();

        if (tid < 32) {
            int r = tid >> 1, c = tid & 1;
            const float* fw = fcw + c*96;
            float s = fcb[c];
            #pragma unroll 8
            for (int d = 0; d < 96; d++) s = fmaf(xh[d*16 + r], fw[d], s);
            pres += s;
            size_t n = nbase + r;
            out[(n*FUTD + t)*2 + c] = pres;
        }
    }
}

extern "C" void kernel_launch(void* const* d_in, const int* in_sizes, int n_in,
                              void* d_out, int out_size)
{
    const float* past    = (const float*)d_in[0];
    const float* obs     = (const float*)d_in[1];
    const float* conv_w  = (const float*)d_in[2];
    const float* conv_b  = (const float*)d_in[3];
    const float* enc_wih = (const float*)d_in[4];
    const float* enc_whh = (const float*)d_in[5];
    const float* enc_bih = (const float*)d_in[6];
    const float* enc_bhh = (const float*)d_in[7];
    const float* mem_p   = (const float*)d_in[8];
    const float* mem_f   = (const float*)d_in[9];
    const float* Wq      = (const float*)d_in[10];
    const float* bq      = (const float*)d_in[11];
    const float* Wk      = (const float*)d_in[12];
    const float* bk      = (const float*)d_in[13];
    const float* Wv      = (const float*)d_in[14];
    const float* bv      = (const float*)d_in[15];
    const float* dec_wih = (const float*)d_in[16];
    const float* dec_whh = (const float*)d_in[17];
    const float* dec_bih = (const float*)d_in[18];
    const float* dec_bhh = (const float*)d_in[19];
    const float* fc_w    = (const float*)d_in[20];
    const float* fc_b    = (const float*)d_in[21];
    float* out = (float*)d_out;

    cudaFuncSetAttribute(attn_kernel,
        cudaFuncAttributeMaxDynamicSharedMemorySize, SMEM_ATTN);

    enc_kernel<<<BD, 144>>>(past, conv_w, conv_b, enc_wih, enc_whh,
                            enc_bih, enc_bhh, Wq, bq);
    kproj_kernel<<<(MD*48 + 255)/256, 256>>>(mem_p, Wk, bk);
    vproj_kernel<<<MD/256, 256>>>(mem_f, Wv, bv);
    wt_kernel<<<(288*96 + 255)/256, 256>>>(dec_wih, dec_whh);

    for (int it = 0; it < NPREDD; it++) {
        attn_kernel<<<dim3(NSLICE, BD/64), 128, SMEM_ATTN>>>();
        combine_kernel<<<64, 384>>>(Wq, bq, it);
    }

    dec_kernel<<<NROWS/16, 288>>>(obs, dec_bih, dec_bhh, fc_w, fc_b, out);
}

// round 10
// speedup vs baseline: 1.0303x; 1.0303x over previous
#include <cuda_runtime.h>
#include <cuda_bf16.h>
#include <math.h>

#define BD 512
#define MD 32768
#define NPREDD 20
#define FUTD 12
#define NROWS (BD*NPREDD)
#define NSLICE 36
#define LOG2E 1.4426950408889634f

// smem: 2 KV buffers
// buf b at b*28160: Kh[64][56] bf16 (7168), Kl (7168), Vh[48][72] bf16 (6912), Vl (6912)
#define KVBUF_B   28160
#define SMEM_ATTN (2*KVBUF_B)

__device__ float g_state[BD*48];
__device__ float g_q[BD*48];
__device__ __nv_bfloat16 g_Kh[MD*48];
__device__ __nv_bfloat16 g_Kl[MD*48];
__device__ __nv_bfloat16 g_Vth[48*MD];
__device__ __nv_bfloat16 g_Vtl[48*MD];
__device__ float g_part[NSLICE*BD*52];
__device__ float g_pred[NROWS*48];
__device__ __nv_bfloat16 g_Wih_h[288*96];
__device__ __nv_bfloat16 g_Wih_l[288*96];
__device__ __nv_bfloat16 g_Whh_h[288*96];
__device__ __nv_bfloat16 g_Whh_l[288*96];

__device__ __forceinline__ float sg_(float x){ return 1.f/(1.f+__expf(-x)); }

__device__ __forceinline__ void cpa16(void* dst, const void* src){
    unsigned ds = (unsigned)__cvta_generic_to_shared(dst);
    asm volatile("cp.async.cg.shared.global [%0], [%1], 16;\n" :: "r"(ds), "l"(src));
}

#define MMA_BF16(c, a0,a1,a2,a3, b0,b1) \
    asm volatile("mma.sync.aligned.m16n8k16.row.col.f32.bf16.bf16.f32 " \
        "{%0,%1,%2,%3}, {%4,%5,%6,%7}, {%8,%9}, {%0,%1,%2,%3};" \
        : "+f"(c[0]), "+f"(c[1]), "+f"(c[2]), "+f"(c[3]) \
        : "r"(a0),"r"(a1),"r"(a2),"r"(a3),"r"(b0),"r"(b1))

__device__ __forceinline__ unsigned ldu32(const __nv_bfloat16* p){
    return *(const unsigned*)p;
}
__device__ __forceinline__ unsigned short us_(__nv_bfloat16 h){
    return *(unsigned short*)&h;
}
__device__ __forceinline__ void split2(float a, float b, unsigned &hi, unsigned &lo){
    __nv_bfloat16 ha = __float2bfloat16(a), hb = __float2bfloat16(b);
    __nv_bfloat16 la = __float2bfloat16(a - __bfloat162float(ha));
    __nv_bfloat16 lb = __float2bfloat16(b - __bfloat162float(hb));
    hi = (unsigned)us_(ha) | ((unsigned)us_(hb) << 16);
    lo = (unsigned)us_(la) | ((unsigned)us_(lb) << 16);
}
__device__ __forceinline__ void splits(float v, __nv_bfloat16* ph, __nv_bfloat16* pl){
    __nv_bfloat16 h = __float2bfloat16(v);
    *ph = h;
    *pl = __float2bfloat16(v - __bfloat162float(h));
}

// ---------- encoder ----------
__global__ void enc_kernel(const float* __restrict__ past,
    const float* __restrict__ cw, const float* __restrict__ cb,
    const float* __restrict__ wih, const float* __restrict__ whh,
    const float* __restrict__ bih, const float* __restrict__ bhh,
    const float* __restrict__ Wq, const float* __restrict__ bq)
{
    __shared__ float se[8][48];
    __shared__ float sh[48];
    __shared__ float sgi[144], sgh[144];
    int b = blockIdx.x, tid = threadIdx.x;
    for (int idx = tid; idx < 8*48; idx += 144) {
        int t = idx/48, c = idx%48;
        float s = cb[c];
        #pragma unroll
        for (int k = 0; k < 3; k++) {
            int tt = t + k - 1;
            if (tt >= 0 && tt < 8) {
                s = fmaf(cw[c*6+k],   past[b*16+tt*2+0], s);
                s = fmaf(cw[c*6+3+k], past[b*16+tt*2+1], s);
            }
        }
        se[t][c] = fmaxf(s, 0.f);
    }
    if (tid < 48) sh[tid] = 0.f;
    __syncthreads();
    for (int t = 0; t < 8; t++) {
        float gi = bih[tid], gh = bhh[tid];
        const float* wi = wih + tid*48;
        const float* wh = whh + tid*48;
        #pragma unroll 8
        for (int d = 0; d < 48; d++) {
            gi = fmaf(se[t][d], wi[d], gi);
            gh = fmaf(sh[d],    wh[d], gh);
        }
        sgi[tid] = gi; sgh[tid] = gh;
        __syncthreads();
        float hn = 0.f;
        if (tid < 48) {
            float r = sg_(sgi[tid]    + sgh[tid]);
            float z = sg_(sgi[48+tid] + sgh[48+tid]);
            float n = tanhf(sgi[96+tid] + r*sgh[96+tid]);
            hn = (1.f-z)*n + z*sh[tid];
        }
        __syncthreads();
        if (tid < 48) sh[tid] = hn;
        __syncthreads();
    }
    if (tid < 48) {
        g_state[b*48+tid] = sh[tid];
        float q = bq[tid];
        const float* w = Wq + tid*48;
        #pragma unroll 8
        for (int d = 0; d < 48; d++) q = fmaf(sh[d], w[d], q);
        g_q[b*48+tid] = q;
    }
}

// ---------- K projection + hi/lo split (m-major) ----------
__global__ void kproj_kernel(const float* __restrict__ mp,
    const float* __restrict__ Wk, const float* __restrict__ bk)
{
    int idx = blockIdx.x*blockDim.x + threadIdx.x;
    if (idx >= MD*48) return;
    int m = idx/48, j = idx - m*48;
    const float* rp = mp + m*48;
    const float* wk = Wk + j*48;
    float sk = bk[j];
    #pragma unroll 8
    for (int d = 0; d < 48; d++) sk = fmaf(rp[d], wk[d], sk);
    splits(sk, &g_Kh[idx], &g_Kl[idx]);
}

// ---------- V projection + hi/lo split, transposed (d-major) ----------
__global__ void vproj_kernel(const float* __restrict__ mf,
    const float* __restrict__ Wv, const float* __restrict__ bv)
{
    __shared__ float sW[48*48];
    __shared__ float sb[48];
    int tid = threadIdx.x;
    for (int i = tid; i < 48*48; i += 256) sW[i] = Wv[i];
    if (tid < 48) sb[tid] = bv[tid];
    __syncthreads();
    int m = blockIdx.x*256 + tid;
    float r[48];
    #pragma unroll 8
    for (int d = 0; d < 48; d++) r[d] = mf[(size_t)m*48 + d];
    #pragma unroll 1
    for (int j = 0; j < 48; j++) {
        float sv = sb[j];
        const float* w = sW + j*48;
        #pragma unroll 8
        for (int d = 0; d < 48; d++) sv = fmaf(r[d], w[d], sv);
        splits(sv, &g_Vth[(size_t)j*MD + m], &g_Vtl[(size_t)j*MD + m]);
    }
}

// ---------- decoder weight hi/lo split ----------
__global__ void wsplit_kernel(const float* __restrict__ wih, const float* __restrict__ whh)
{
    int i = blockIdx.x*blockDim.x + threadIdx.x;
    if (i < 288*96) {
        splits(wih[i], &g_Wih_h[i], &g_Wih_l[i]);
        splits(whh[i], &g_Whh_h[i], &g_Whh_l[i]);
    }
}

// ---------- prefetch helper ----------
__device__ __forceinline__ void prefetch_chunk(char* base, int m0, int tid){
    #pragma unroll
    for (int i = tid; i < 768; i += 128) {
        int arr = i / 384;
        int r = (i % 384) / 6, seg = i % 6;
        const char* src = (const char*)(arr ? g_Kl : g_Kh) + ((size_t)(m0+r)*48)*2 + seg*16;
        cpa16(base + arr*7168 + r*112 + seg*16, src);
    }
    #pragma unroll
    for (int i = tid; i < 768; i += 128) {
        int arr = i / 384;
        int r = (i % 384) / 8, seg = i % 8;
        const char* src = (const char*)(arr ? g_Vtl : g_Vth) + ((size_t)r*MD + m0)*2 + seg*16;
        cpa16(base + 14336 + arr*6912 + r*144 + seg*16, src);
    }
}

// ---------- attention: register-resident FA2, bf16-split HMMA ----------
__global__ void __launch_bounds__(128,2) attn_kernel()
{
    extern __shared__ char sm[];
    int tid = threadIdx.x, lane = tid & 31, w = tid >> 5;
    int gid = lane >> 2, tg = lane & 3;
    int qbase = blockIdx.y * 64;
    int s = blockIdx.x;
    int m_start = (s < 8) ? s*960 : 7680 + (s-8)*896;
    int nch = (s < 8) ? 15 : 14;

    // q fragments from gmem, pre-scaled by log2(e) (softmax in exp2 domain)
    unsigned qh[3][4], ql[3][4];
    {
        int r0 = qbase + w*16 + gid, r1 = r0 + 8;
        const float* Q0 = g_q + (size_t)r0*48;
        const float* Q1 = g_q + (size_t)r1*48;
        #pragma unroll
        for (int j = 0; j < 3; j++) {
            int c = j*16 + tg*2;
            split2(Q0[c]*LOG2E,   Q0[c+1]*LOG2E, qh[j][0], ql[j][0]);
            split2(Q1[c]*LOG2E,   Q1[c+1]*LOG2E, qh[j][1], ql[j][1]);
            split2(Q0[c+8]*LOG2E, Q0[c+9]*LOG2E, qh[j][2], ql[j][2]);
            split2(Q1[c+8]*LOG2E, Q1[c+9]*LOG2E, qh[j][3], ql[j][3]);
        }
    }

    prefetch_chunk(sm, m_start, tid);
    asm volatile("cp.async.commit_group;\n");

    float O[6][4];
    #pragma unroll
    for (int dt = 0; dt < 6; dt++) { O[dt][0]=0.f; O[dt][1]=0.f; O[dt][2]=0.f; O[dt][3]=0.f; }
    float rm = -1e30f, rs0 = 0.f, rs1 = 0.f;

    for (int c = 0; c < nch; c++) {
        asm volatile("cp.async.wait_group 0;\n" ::: "memory");
        __syncthreads();
        if (c + 1 < nch)
            prefetch_chunk(sm + ((c+1)&1)*KVBUF_B, m_start + (c+1)*64, tid);
        asm volatile("cp.async.commit_group;\n");

        const __nv_bfloat16* Kh = (const __nv_bfloat16*)(sm + (c&1)*KVBUF_B);
        const __nv_bfloat16* Kl = Kh + 64*56;
        const __nv_bfloat16* Vh = (const __nv_bfloat16*)(sm + (c&1)*KVBUF_B + 14336);
        const __nv_bfloat16* Vl = Vh + 48*72;

        // ---- QK^T ----
        float Sc[8][4];
        #pragma unroll
        for (int nt = 0; nt < 8; nt++) { Sc[nt][0]=0.f; Sc[nt][1]=0.f; Sc[nt][2]=0.f; Sc[nt][3]=0.f; }
        #pragma unroll
        for (int j = 0; j < 3; j++) {
            int kc = j*16 + tg*2;
            #pragma unroll
            for (int nt = 0; nt < 8; nt++) {
                const __nv_bfloat16* kr = Kh + (nt*8+gid)*56 + kc;
                const __nv_bfloat16* lr = Kl + (nt*8+gid)*56 + kc;
                unsigned kh0 = ldu32(kr), kh1 = ldu32(kr + 8);
                unsigned kl0 = ldu32(lr), kl1 = ldu32(lr + 8);
                MMA_BF16(Sc[nt], qh[j][0],qh[j][1],qh[j][2],qh[j][3], kh0,kh1);
                MMA_BF16(Sc[nt], qh[j][0],qh[j][1],qh[j][2],qh[j][3], kl0,kl1);
                MMA_BF16(Sc[nt], ql[j][0],ql[j][1],ql[j][2],ql[j][3], kh0,kh1);
            }
        }

        // ---- warp-uniform online max; rescale only when it moves ----
        float mw = Sc[0][0];
        #pragma unroll
        for (int nt = 0; nt < 8; nt++) {
            mw = fmaxf(mw, fmaxf(Sc[nt][0], Sc[nt][1]));
            mw = fmaxf(mw, fmaxf(Sc[nt][2], Sc[nt][3]));
        }
        #pragma unroll
        for (int off = 16; off; off >>= 1)
            mw = fmaxf(mw, __shfl_xor_sync(0xffffffffu, mw, off));
        if (mw > rm) {
            float f = exp2f(rm - mw);
            rm = mw;
            rs0 *= f; rs1 *= f;
            #pragma unroll
            for (int dt = 0; dt < 6; dt++) {
                O[dt][0] *= f; O[dt][1] *= f;
                O[dt][2] *= f; O[dt][3] *= f;
            }
        }

        // ---- exp2 + PV in two halves ----
        #pragma unroll
        for (int half = 0; half < 2; half++) {
            unsigned p01h[4], p01l[4], p23h[4], p23l[4];
            #pragma unroll
            for (int k = 0; k < 4; k++) {
                int nt = half*4 + k;
                float p0 = exp2f(Sc[nt][0] - rm);
                float p1 = exp2f(Sc[nt][1] - rm);
                float p2 = exp2f(Sc[nt][2] - rm);
                float p3 = exp2f(Sc[nt][3] - rm);
                rs0 += p0 + p1; rs1 += p2 + p3;
                split2(p0, p1, p01h[k], p01l[k]);
                split2(p2, p3, p23h[k], p23l[k]);
            }
            #pragma unroll
            for (int tt = 0; tt < 2; tt++) {
                int t = half*2 + tt;
                unsigned ah0 = p01h[2*tt],   ah1 = p23h[2*tt];
                unsigned ah2 = p01h[2*tt+1], ah3 = p23h[2*tt+1];
                unsigned al0 = p01l[2*tt],   al1 = p23l[2*tt];
                unsigned al2 = p01l[2*tt+1], al3 = p23l[2*tt+1];
                int mk = t*16 + tg*2;
                #pragma unroll
                for (int dt = 0; dt < 6; dt++) {
                    const __nv_bfloat16* vr = Vh + (dt*8+gid)*72 + mk;
                    const __nv_bfloat16* wr = Vl + (dt*8+gid)*72 + mk;
                    unsigned vh0 = ldu32(vr), vh1 = ldu32(vr + 8);
                    unsigned vl0 = ldu32(wr), vl1 = ldu32(wr + 8);
                    MMA_BF16(O[dt], ah0,ah1,ah2,ah3, vh0,vh1);
                    MMA_BF16(O[dt], ah0,ah1,ah2,ah3, vl0,vl1);
                    MMA_BF16(O[dt], al0,al1,al2,al3, vh0,vh1);
                }
            }
        }
    }

    // ---- epilogue ----
    rs0 += __shfl_xor_sync(0xffffffffu, rs0, 1);
    rs0 += __shfl_xor_sync(0xffffffffu, rs0, 2);
    rs1 += __shfl_xor_sync(0xffffffffu, rs1, 1);
    rs1 += __shfl_xor_sync(0xffffffffu, rs1, 2);

    int gq0 = qbase + w*16 + gid, gq1 = gq0 + 8;
    float* P0 = g_part + ((size_t)s*BD + gq0)*52;
    float* P1 = g_part + ((size_t)s*BD + gq1)*52;
    #pragma unroll
    for (int dt = 0; dt < 6; dt++) {
        int col = dt*8 + tg*2;
        P0[col]   = O[dt][0];
        P0[col+1] = O[dt][1];
        P1[col]   = O[dt][2];
        P1[col+1] = O[dt][3];
    }
    if (tg == 0) {
        P0[48] = rm; P0[49] = rs0;
        P1[48] = rm; P1[49] = rs1;
    }
}

// ---------- combine partials + emit pred + next q (8 q per block) ----------
__global__ void combine_kernel(const float* __restrict__ Wq, const float* __restrict__ bq,
                               int iter)
{
    __shared__ float sc[8][48];
    int t = threadIdx.x;
    int ql = t / 48, d = t - ql*48;
    int q = blockIdx.x*8 + ql;
    float gm = -1e30f;
    #pragma unroll 4
    for (int s = 0; s < NSLICE; s++)
        gm = fmaxf(gm, g_part[((size_t)s*BD+q)*52 + 48]);
    float tot = 0.f, av = 0.f;
    #pragma unroll 4
    for (int s = 0; s < NSLICE; s++) {
        const float* P = g_part + ((size_t)s*BD+q)*52;
        float e = exp2f(P[48] - gm);
        tot = fmaf(P[49], e, tot);
        av  = fmaf(P[d],  e, av);
    }
    float att = av / tot;
    g_pred[(q*NPREDD + iter)*48 + d] = att;
    sc[ql][d] = g_q[q*48+d] + att;
    __syncthreads();
    float qn = bq[d];
    const float* w = Wq + d*48;
    #pragma unroll 8
    for (int k = 0; k < 48; k++) qn = fmaf(sc[ql][k], w[k], qn);
    g_q[q*48+d] = qn;
}

// ---------- decoder: GRU(96) x 12 with bf16-split HMMA, 64 rows/CTA ----------
#define XST 104   // xh row stride (bf16 elems)
__global__ void __launch_bounds__(256,2) dec_kernel(
    const float* __restrict__ obs,
    const float* __restrict__ bih, const float* __restrict__ bhh,
    const float* __restrict__ fcw, const float* __restrict__ fcb,
    float* __restrict__ out)
{
    __shared__ __nv_bfloat16 xh_h[64*XST];
    __shared__ __nv_bfloat16 xh_l[64*XST];
    __shared__ float ghs[288*68];
    int tid = threadIdx.x, lane = tid & 31, w = tid >> 5;
    int gid = lane >> 2, tg = lane & 3;
    int nbase = blockIdx.x*64;
    int rw = (w >> 1)*16;      // warp row base
    int nwb = (w & 1)*144;     // warp col base

    for (int i = tid; i < 64*96; i += 256) {
        int r = i / 96, d = i - r*96;
        int n = nbase + r;
        float v = (d < 48) ? g_state[(n/NPREDD)*48 + d] : g_pred[(size_t)n*48 + (d-48)];
        splits(v, &xh_h[r*XST + d], &xh_l[r*XST + d]);
    }
    float pres = 0.f;
    if (tid < 128) {
        int n = nbase + (tid >> 1);
        pres = obs[(n/NPREDD)*16 + 14 + (tid & 1)];
    }
    __syncthreads();

    for (int t = 0; t < FUTD; t++) {
        const __nv_bfloat16* Wh = t ? g_Whh_h : g_Wih_h;
        const __nv_bfloat16* Wl = t ? g_Whh_l : g_Wih_l;
        const float* b0 = t ? bhh : bih;
        const float* b1 = t ? bih : bhh;

        float C[18][4];
        #pragma unroll
        for (int nt = 0; nt < 18; nt++) { C[nt][0]=0.f; C[nt][1]=0.f; C[nt][2]=0.f; C[nt][3]=0.f; }

        #pragma unroll 1
        for (int kt = 0; kt < 6; kt++) {
            int kc = kt*16 + tg*2;
            const __nv_bfloat16* A0 = xh_h + (rw+gid)*XST + kc;
            const __nv_bfloat16* A1 = xh_h + (rw+gid+8)*XST + kc;
            const __nv_bfloat16* B0 = xh_l + (rw+gid)*XST + kc;
            const __nv_bfloat16* B1 = xh_l + (rw+gid+8)*XST + kc;
            unsigned ah0 = ldu32(A0),   ah1 = ldu32(A1);
            unsigned ah2 = ldu32(A0+8), ah3 = ldu32(A1+8);
            unsigned al0 = ldu32(B0),   al1 = ldu32(B1);
            unsigned al2 = ldu32(B0+8), al3 = ldu32(B1+8);
            #pragma unroll
            for (int nt = 0; nt < 18; nt++) {
                int j = nwb + nt*8 + gid;
                const __nv_bfloat16* Bh = Wh + j*96 + kc;
                const __nv_bfloat16* Bl = Wl + j*96 + kc;
                unsigned bh0 = ldu32(Bh), bh1 = ldu32(Bh + 8);
                unsigned bl0 = ldu32(Bl), bl1 = ldu32(Bl + 8);
                MMA_BF16(C[nt], ah0,ah1,ah2,ah3, bh0,bh1);
                MMA_BF16(C[nt], ah0,ah1,ah2,ah3, bl0,bl1);
                MMA_BF16(C[nt], al0,al1,al2,al3, bh0,bh1);
            }
        }
        #pragma unroll
        for (int nt = 0; nt < 18; nt++) {
            int cb = nwb + nt*8 + tg*2;
            ghs[cb*68 + rw+gid]       = C[nt][0];
            ghs[(cb+1)*68 + rw+gid]   = C[nt][1];
            ghs[cb*68 + rw+gid+8]     = C[nt][2];
            ghs[(cb+1)*68 + rw+gid+8] = C[nt][3];
        }
        __syncthreads();

        // pointwise GRU update
        for (int i = tid; i < 64*96; i += 256) {
            int r = i & 63, d = i >> 6;
            float gr = ghs[d*68 + r]       + b0[d];
            float gz = ghs[(96+d)*68 + r]  + b0[96+d];
            float gn = ghs[(192+d)*68 + r] + b0[192+d];
            float rg = sg_(gr + b1[d]);
            float z  = sg_(gz + b1[96+d]);
            float nn, h;
            if (t == 0) {
                nn = tanhf(gn + rg*b1[192+d]);
                h = (1.f - z)*nn;
            } else {
                float hold = __bfloat162float(xh_h[r*XST + d]) + __bfloat162float(xh_l[r*XST + d]);
                nn = tanhf(b1[192+d] + rg*gn);
                h = (1.f - z)*nn + z*hold;
            }
            splits(h, &xh_h[r*XST + d], &xh_l[r*XST + d]);
        }
        __syncthreads();

        // fc + output
        if (tid < 128) {
            int r = tid >> 1, c = tid & 1;
            const float* fw = fcw + c*96;
            float s = fcb[c];
            #pragma unroll 8
            for (int d = 0; d < 96; d++) {
                float hv = __bfloat162float(xh_h[r*XST + d]) + __bfloat162float(xh_l[r*XST + d]);
                s = fmaf(hv, fw[d], s);
            }
            pres += s;
            size_t n = nbase + r;
            out[(n*FUTD + t)*2 + c] = pres;
        }
    }
}

extern "C" void kernel_launch(void* const* d_in, const int* in_sizes, int n_in,
                              void* d_out, int out_size)
{
    const float* past    = (const float*)d_in[0];
    const float* obs     = (const float*)d_in[1];
    const float* conv_w  = (const float*)d_in[2];
    const float* conv_b  = (const float*)d_in[3];
    const float* enc_wih = (const float*)d_in[4];
    const float* enc_whh = (const float*)d_in[5];
    const float* enc_bih = (const float*)d_in[6];
    const float* enc_bhh = (const float*)d_in[7];
    const float* mem_p   = (const float*)d_in[8];
    const float* mem_f   = (const float*)d_in[9];
    const float* Wq      = (const float*)d_in[10];
    const float* bq      = (const float*)d_in[11];
    const float* Wk      = (const float*)d_in[12];
    const float* bk      = (const float*)d_in[13];
    const float* Wv      = (const float*)d_in[14];
    const float* bv      = (const float*)d_in[15];
    const float* dec_wih = (const float*)d_in[16];
    const float* dec_whh = (const float*)d_in[17];
    const float* dec_bih = (const float*)d_in[18];
    const float* dec_bhh = (const float*)d_in[19];
    const float* fc_w    = (const float*)d_in[20];
    const float* fc_b    = (const float*)d_in[21];
    float* out = (float*)d_out;

    cudaFuncSetAttribute(attn_kernel,
        cudaFuncAttributeMaxDynamicSharedMemorySize, SMEM_ATTN);

    enc_kernel<<<BD, 144>>>(past, conv_w, conv_b, enc_wih, enc_whh,
                            enc_bih, enc_bhh, Wq, bq);
    kproj_kernel<<<(MD*48 + 255)/256, 256>>>(mem_p, Wk, bk);
    vproj_kernel<<<MD/256, 256>>>(mem_f, Wv, bv);
    wsplit_kernel<<<(288*96 + 255)/256, 256>>>(dec_wih, dec_whh);

    for (int it = 0; it < NPREDD; it++) {
        attn_kernel<<<dim3(NSLICE, BD/64), 128, SMEM_ATTN>>>();
        combine_kernel<<<64, 384>>>(Wq, bq, it);
    }

    dec_kernel<<<NROWS/64, 256>>>(obs, dec_bih, dec_bhh, fc_w, fc_b, out);
}

// round 11
// speedup vs baseline: 1.1875x; 1.1526x over previous
#include <cuda_runtime.h>
#include <cuda_bf16.h>
#include <math.h>

#define BD 512
#define MD 32768
#define NPREDD 20
#define FUTD 12
#define NROWS (BD*NPREDD)
#define NSLICE 36

// attn smem: 2 KV buffers + Q staging
#define KVBUF_B   28160
#define OFF_Q     (2*KVBUF_B)
#define SMEM_ATTN (OFF_Q + 64*48*4)

// decoder smem: W (hi+lo) swizzled + small bias/fc tables
#define DEC_W_BYTES (288*96*2*2)            // 110592
#define DEC_SMEM    (DEC_W_BYTES + 576*4)   // +2304 = 112896

__device__ float g_state[BD*48];
__device__ float g_q[BD*48];
__device__ __nv_bfloat16 g_Kh[MD*48];
__device__ __nv_bfloat16 g_Kl[MD*48];
__device__ __nv_bfloat16 g_Vth[48*MD];
__device__ __nv_bfloat16 g_Vtl[48*MD];
__device__ float g_part[NSLICE*BD*52];
__device__ float g_pred[NROWS*48];
__device__ __nv_bfloat16 g_Wih_h[288*96];
__device__ __nv_bfloat16 g_Wih_l[288*96];
__device__ __nv_bfloat16 g_Whh_h[288*96];
__device__ __nv_bfloat16 g_Whh_l[288*96];

__device__ __forceinline__ float sg_(float x){ return 1.f/(1.f+__expf(-x)); }

__device__ __forceinline__ void cpa16(void* dst, const void* src){
    unsigned ds = (unsigned)__cvta_generic_to_shared(dst);
    asm volatile("cp.async.cg.shared.global [%0], [%1], 16;\n" :: "r"(ds), "l"(src));
}

#define MMA_BF16(c, a0,a1,a2,a3, b0,b1) \
    asm volatile("mma.sync.aligned.m16n8k16.row.col.f32.bf16.bf16.f32 " \
        "{%0,%1,%2,%3}, {%4,%5,%6,%7}, {%8,%9}, {%0,%1,%2,%3};" \
        : "+f"(c[0]), "+f"(c[1]), "+f"(c[2]), "+f"(c[3]) \
        : "r"(a0),"r"(a1),"r"(a2),"r"(a3),"r"(b0),"r"(b1))

__device__ __forceinline__ unsigned ldu32(const __nv_bfloat16* p){
    return *(const unsigned*)p;
}
__device__ __forceinline__ unsigned short us_(__nv_bfloat16 h){
    return *(unsigned short*)&h;
}
__device__ __forceinline__ void split2(float a, float b, unsigned &hi, unsigned &lo){
    __nv_bfloat16 ha = __float2bfloat16(a), hb = __float2bfloat16(b);
    __nv_bfloat16 la = __float2bfloat16(a - __bfloat162float(ha));
    __nv_bfloat16 lb = __float2bfloat16(b - __bfloat162float(hb));
    hi = (unsigned)us_(ha) | ((unsigned)us_(hb) << 16);
    lo = (unsigned)us_(la) | ((unsigned)us_(lb) << 16);
}
__device__ __forceinline__ void splits(float v, __nv_bfloat16* ph, __nv_bfloat16* pl){
    __nv_bfloat16 h = __float2bfloat16(v);
    *ph = h;
    *pl = __float2bfloat16(v - __bfloat162float(h));
}
__device__ __forceinline__ float bflo(unsigned u){
    return __bfloat162float(__ushort_as_bfloat16((unsigned short)(u & 0xffffu)));
}
__device__ __forceinline__ float bfhi(unsigned u){
    return __bfloat162float(__ushort_as_bfloat16((unsigned short)(u >> 16)));
}

// ---------- encoder ----------
__global__ void enc_kernel(const float* __restrict__ past,
    const float* __restrict__ cw, const float* __restrict__ cb,
    const float* __restrict__ wih, const float* __restrict__ whh,
    const float* __restrict__ bih, const float* __restrict__ bhh,
    const float* __restrict__ Wq, const float* __restrict__ bq)
{
    __shared__ float se[8][48];
    __shared__ float sh[48];
    __shared__ float sgi[144], sgh[144];
    int b = blockIdx.x, tid = threadIdx.x;
    for (int idx = tid; idx < 8*48; idx += 144) {
        int t = idx/48, c = idx%48;
        float s = cb[c];
        #pragma unroll
        for (int k = 0; k < 3; k++) {
            int tt = t + k - 1;
            if (tt >= 0 && tt < 8) {
                s = fmaf(cw[c*6+k],   past[b*16+tt*2+0], s);
                s = fmaf(cw[c*6+3+k], past[b*16+tt*2+1], s);
            }
        }
        se[t][c] = fmaxf(s, 0.f);
    }
    if (tid < 48) sh[tid] = 0.f;
    __syncthreads();
    for (int t = 0; t < 8; t++) {
        float gi = bih[tid], gh = bhh[tid];
        const float* wi = wih + tid*48;
        const float* wh = whh + tid*48;
        #pragma unroll 8
        for (int d = 0; d < 48; d++) {
            gi = fmaf(se[t][d], wi[d], gi);
            gh = fmaf(sh[d],    wh[d], gh);
        }
        sgi[tid] = gi; sgh[tid] = gh;
        __syncthreads();
        float hn = 0.f;
        if (tid < 48) {
            float r = sg_(sgi[tid]    + sgh[tid]);
            float z = sg_(sgi[48+tid] + sgh[48+tid]);
            float n = tanhf(sgi[96+tid] + r*sgh[96+tid]);
            hn = (1.f-z)*n + z*sh[tid];
        }
        __syncthreads();
        if (tid < 48) sh[tid] = hn;
        __syncthreads();
    }
    if (tid < 48) {
        g_state[b*48+tid] = sh[tid];
        float q = bq[tid];
        const float* w = Wq + tid*48;
        #pragma unroll 8
        for (int d = 0; d < 48; d++) q = fmaf(sh[d], w[d], q);
        g_q[b*48+tid] = q;
    }
}

// ---------- K projection + hi/lo split (m-major) ----------
__global__ void kproj_kernel(const float* __restrict__ mp,
    const float* __restrict__ Wk, const float* __restrict__ bk)
{
    int idx = blockIdx.x*blockDim.x + threadIdx.x;
    if (idx >= MD*48) return;
    int m = idx/48, j = idx - m*48;
    const float* rp = mp + m*48;
    const float* wk = Wk + j*48;
    float sk = bk[j];
    #pragma unroll 8
    for (int d = 0; d < 48; d++) sk = fmaf(rp[d], wk[d], sk);
    splits(sk, &g_Kh[idx], &g_Kl[idx]);
}

// ---------- V projection + hi/lo split, transposed (d-major) ----------
__global__ void vproj_kernel(const float* __restrict__ mf,
    const float* __restrict__ Wv, const float* __restrict__ bv)
{
    __shared__ float sW[48*48];
    __shared__ float sb[48];
    int tid = threadIdx.x;
    for (int i = tid; i < 48*48; i += 256) sW[i] = Wv[i];
    if (tid < 48) sb[tid] = bv[tid];
    __syncthreads();
    int m = blockIdx.x*256 + tid;
    float r[48];
    #pragma unroll 8
    for (int d = 0; d < 48; d++) r[d] = mf[(size_t)m*48 + d];
    #pragma unroll 1
    for (int j = 0; j < 48; j++) {
        float sv = sb[j];
        const float* w = sW + j*48;
        #pragma unroll 8
        for (int d = 0; d < 48; d++) sv = fmaf(r[d], w[d], sv);
        splits(sv, &g_Vth[(size_t)j*MD + m], &g_Vtl[(size_t)j*MD + m]);
    }
}

// ---------- decoder weight hi/lo split (row-major [288][96]) ----------
__global__ void wsplit_kernel(const float* __restrict__ wih, const float* __restrict__ whh)
{
    int i = blockIdx.x*blockDim.x + threadIdx.x;
    if (i < 288*96) {
        splits(wih[i], &g_Wih_h[i], &g_Wih_l[i]);
        splits(whh[i], &g_Whh_h[i], &g_Whh_l[i]);
    }
}

// ---------- prefetch helper (attn) ----------
__device__ __forceinline__ void prefetch_chunk(char* base, int m0, int tid){
    #pragma unroll
    for (int i = tid; i < 768; i += 128) {
        int arr = i / 384;
        int r = (i % 384) / 6, seg = i % 6;
        const char* src = (const char*)(arr ? g_Kl : g_Kh) + ((size_t)(m0+r)*48)*2 + seg*16;
        cpa16(base + arr*7168 + r*112 + seg*16, src);
    }
    #pragma unroll
    for (int i = tid; i < 768; i += 128) {
        int arr = i / 384;
        int r = (i % 384) / 8, seg = i % 8;
        const char* src = (const char*)(arr ? g_Vtl : g_Vth) + ((size_t)r*MD + m0)*2 + seg*16;
        cpa16(base + 14336 + arr*6912 + r*144 + seg*16, src);
    }
}

// ---------- attention: register-resident FA2, bf16-split HMMA (R7 proven) ----------
__global__ void __launch_bounds__(128,2) attn_kernel()
{
    extern __shared__ char sm[];
    int tid = threadIdx.x, lane = tid & 31, w = tid >> 5;
    int gid = lane >> 2, tg = lane & 3;
    int qbase = blockIdx.y * 64;
    int s = blockIdx.x;
    int m_start = (s < 8) ? s*960 : 7680 + (s-8)*896;
    int nch = (s < 8) ? 15 : 14;

    float* sQ = (float*)(sm + OFF_Q);
    for (int i = tid; i < 64*48; i += 128) sQ[i] = g_q[qbase*48 + i];
    __syncthreads();

    unsigned qh[3][4], ql[3][4];
    {
        int r0 = w*16 + gid, r1 = r0 + 8;
        #pragma unroll
        for (int j = 0; j < 3; j++) {
            int c = j*16 + tg*2;
            split2(sQ[r0*48 + c],     sQ[r0*48 + c + 1],     qh[j][0], ql[j][0]);
            split2(sQ[r1*48 + c],     sQ[r1*48 + c + 1],     qh[j][1], ql[j][1]);
            split2(sQ[r0*48 + c + 8], sQ[r0*48 + c + 9],     qh[j][2], ql[j][2]);
            split2(sQ[r1*48 + c + 8], sQ[r1*48 + c + 9],     qh[j][3], ql[j][3]);
        }
    }

    prefetch_chunk(sm, m_start, tid);
    asm volatile("cp.async.commit_group;\n");

    float O[6][4];
    #pragma unroll
    for (int dt = 0; dt < 6; dt++) { O[dt][0]=0.f; O[dt][1]=0.f; O[dt][2]=0.f; O[dt][3]=0.f; }
    float rm0 = -1e30f, rm1 = -1e30f, rs0 = 0.f, rs1 = 0.f;

    for (int c = 0; c < nch; c++) {
        asm volatile("cp.async.wait_group 0;\n" ::: "memory");
        __syncthreads();
        if (c + 1 < nch)
            prefetch_chunk(sm + ((c+1)&1)*KVBUF_B, m_start + (c+1)*64, tid);
        asm volatile("cp.async.commit_group;\n");

        const __nv_bfloat16* Kh = (const __nv_bfloat16*)(sm + (c&1)*KVBUF_B);
        const __nv_bfloat16* Kl = Kh + 64*56;
        const __nv_bfloat16* Vh = (const __nv_bfloat16*)(sm + (c&1)*KVBUF_B + 14336);
        const __nv_bfloat16* Vl = Vh + 48*72;

        float Sc[8][4];
        #pragma unroll
        for (int nt = 0; nt < 8; nt++) { Sc[nt][0]=0.f; Sc[nt][1]=0.f; Sc[nt][2]=0.f; Sc[nt][3]=0.f; }
        #pragma unroll
        for (int j = 0; j < 3; j++) {
            int kc = j*16 + tg*2;
            #pragma unroll
            for (int nt = 0; nt < 8; nt++) {
                const __nv_bfloat16* kr = Kh + (nt*8+gid)*56 + kc;
                const __nv_bfloat16* lr = Kl + (nt*8+gid)*56 + kc;
                unsigned kh0 = ldu32(kr), kh1 = ldu32(kr + 8);
                unsigned kl0 = ldu32(lr), kl1 = ldu32(lr + 8);
                MMA_BF16(Sc[nt], qh[j][0],qh[j][1],qh[j][2],qh[j][3], kh0,kh1);
                MMA_BF16(Sc[nt], qh[j][0],qh[j][1],qh[j][2],qh[j][3], kl0,kl1);
                MMA_BF16(Sc[nt], ql[j][0],ql[j][1],ql[j][2],ql[j][3], kh0,kh1);
            }
        }

        float m0 = Sc[0][0], m1 = Sc[0][2];
        #pragma unroll
        for (int nt = 0; nt < 8; nt++) {
            m0 = fmaxf(m0, fmaxf(Sc[nt][0], Sc[nt][1]));
            m1 = fmaxf(m1, fmaxf(Sc[nt][2], Sc[nt][3]));
        }
        m0 = fmaxf(m0, __shfl_xor_sync(0xffffffffu, m0, 1));
        m0 = fmaxf(m0, __shfl_xor_sync(0xffffffffu, m0, 2));
        m1 = fmaxf(m1, __shfl_xor_sync(0xffffffffu, m1, 1));
        m1 = fmaxf(m1, __shfl_xor_sync(0xffffffffu, m1, 2));
        float nm0 = fmaxf(rm0, m0), nm1 = fmaxf(rm1, m1);
        float f0 = __expf(rm0 - nm0), f1 = __expf(rm1 - nm1);
        rm0 = nm0; rm1 = nm1;
        rs0 *= f0; rs1 *= f1;
        #pragma unroll
        for (int dt = 0; dt < 6; dt++) {
            O[dt][0] *= f0; O[dt][1] *= f0;
            O[dt][2] *= f1; O[dt][3] *= f1;
        }

        #pragma unroll
        for (int half = 0; half < 2; half++) {
            unsigned p01h[4], p01l[4], p23h[4], p23l[4];
            #pragma unroll
            for (int k = 0; k < 4; k++) {
                int nt = half*4 + k;
                float p0 = __expf(Sc[nt][0] - nm0);
                float p1 = __expf(Sc[nt][1] - nm0);
                float p2 = __expf(Sc[nt][2] - nm1);
                float p3 = __expf(Sc[nt][3] - nm1);
                rs0 += p0 + p1; rs1 += p2 + p3;
                split2(p0, p1, p01h[k], p01l[k]);
                split2(p2, p3, p23h[k], p23l[k]);
            }
            #pragma unroll
            for (int tt = 0; tt < 2; tt++) {
                int t = half*2 + tt;
                unsigned ah0 = p01h[2*tt],   ah1 = p23h[2*tt];
                unsigned ah2 = p01h[2*tt+1], ah3 = p23h[2*tt+1];
                unsigned al0 = p01l[2*tt],   al1 = p23l[2*tt];
                unsigned al2 = p01l[2*tt+1], al3 = p23l[2*tt+1];
                int mk = t*16 + tg*2;
                #pragma unroll
                for (int dt = 0; dt < 6; dt++) {
                    const __nv_bfloat16* vr = Vh + (dt*8+gid)*72 + mk;
                    const __nv_bfloat16* wr = Vl + (dt*8+gid)*72 + mk;
                    unsigned vh0 = ldu32(vr), vh1 = ldu32(vr + 8);
                    unsigned vl0 = ldu32(wr), vl1 = ldu32(wr + 8);
                    MMA_BF16(O[dt], ah0,ah1,ah2,ah3, vh0,vh1);
                    MMA_BF16(O[dt], ah0,ah1,ah2,ah3, vl0,vl1);
                    MMA_BF16(O[dt], al0,al1,al2,al3, vh0,vh1);
                }
            }
        }
    }

    rs0 += __shfl_xor_sync(0xffffffffu, rs0, 1);
    rs0 += __shfl_xor_sync(0xffffffffu, rs0, 2);
    rs1 += __shfl_xor_sync(0xffffffffu, rs1, 1);
    rs1 += __shfl_xor_sync(0xffffffffu, rs1, 2);

    int gq0 = qbase + w*16 + gid, gq1 = gq0 + 8;
    float* P0 = g_part + ((size_t)s*BD + gq0)*52;
    float* P1 = g_part + ((size_t)s*BD + gq1)*52;
    #pragma unroll
    for (int dt = 0; dt < 6; dt++) {
        int col = dt*8 + tg*2;
        P0[col]   = O[dt][0];
        P0[col+1] = O[dt][1];
        P1[col]   = O[dt][2];
        P1[col+1] = O[dt][3];
    }
    if (tg == 0) {
        P0[48] = rm0; P0[49] = rs0;
        P1[48] = rm1; P1[49] = rs1;
    }
}

// ---------- combine partials + emit pred + next q (8 q per block) ----------
__global__ void combine_kernel(const float* __restrict__ Wq, const float* __restrict__ bq,
                               int iter)
{
    __shared__ float sc[8][48];
    int t = threadIdx.x;
    int ql = t / 48, d = t - ql*48;
    int q = blockIdx.x*8 + ql;
    float gm = -1e30f;
    #pragma unroll 4
    for (int s = 0; s < NSLICE; s++)
        gm = fmaxf(gm, g_part[((size_t)s*BD+q)*52 + 48]);
    float tot = 0.f, av = 0.f;
    #pragma unroll 4
    for (int s = 0; s < NSLICE; s++) {
        const float* P = g_part + ((size_t)s*BD+q)*52;
        float e = __expf(P[48] - gm);
        tot = fmaf(P[49], e, tot);
        av  = fmaf(P[d],  e, av);
    }
    float att = av / tot;
    g_pred[(q*NPREDD + iter)*48 + d] = att;
    sc[ql][d] = g_q[q*48+d] + att;
    __syncthreads();
    float qn = bq[d];
    const float* w = Wq + d*48;
    #pragma unroll 8
    for (int k = 0; k < 48; k++) qn = fmaf(sc[ql][k], w[k], qn);
    g_q[q*48+d] = qn;
}

// ---------- decoder: register-resident HMMA GRU, 64 rows/CTA, no loop barriers ----
__device__ __forceinline__ float info_at(int n, int d){
    return (d < 48) ? g_state[(n/NPREDD)*48 + d] : g_pred[(size_t)n*48 + (d-48)];
}
__device__ __forceinline__ void stageW(unsigned* Wh32, unsigned* Wl32,
    const __nv_bfloat16* gh, const __nv_bfloat16* gl, int tid)
{
    const unsigned* sh = (const unsigned*)gh;
    const unsigned* sl = (const unsigned*)gl;
    for (int i = tid; i < 288*48; i += 128) {
        int j = i / 48, kk = i - j*48;
        int u = j*48 + (kk ^ (((j>>1)&3)*4));
        Wh32[u] = sh[i];
        Wl32[u] = sl[i];
    }
}

__global__ void __launch_bounds__(128,2) dec_kernel(
    const float* __restrict__ obs,
    const float* __restrict__ bih, const float* __restrict__ bhh,
    const float* __restrict__ fcw, const float* __restrict__ fcb,
    float* __restrict__ out)
{
    extern __shared__ char dsm[];
    unsigned* Wh32 = (unsigned*)dsm;                 // 288*48 uints (swizzled)
    unsigned* Wl32 = Wh32 + 288*48;
    float* sbrz = (float*)(dsm + DEC_W_BYTES);       // 192
    float* sbin = sbrz + 192;                        // 96
    float* sbhn = sbin + 96;                         // 96
    float* sfc  = sbhn + 96;                         // 192

    int tid = threadIdx.x, lane = tid & 31, w = tid >> 5;
    int gid = lane >> 2, tg = lane & 3;
    int nbase = blockIdx.x*64;
    int r0 = nbase + w*16 + gid, r1 = r0 + 8;

    for (int i = tid; i < 192; i += 128) { sbrz[i] = bih[i] + bhh[i]; sfc[i] = fcw[i]; }
    for (int i = tid; i < 96; i += 128)  { sbin[i] = bih[192+i]; sbhn[i] = bhh[192+i]; }
    stageW(Wh32, Wl32, g_Wih_h, g_Wih_l, tid);

    // A fragments from info = [state | pred]
    unsigned ah[6][4], al[6][4];
    #pragma unroll
    for (int kt = 0; kt < 6; kt++) {
        int c = kt*16 + tg*2;
        split2(info_at(r0,c),   info_at(r0,c+1), ah[kt][0], al[kt][0]);
        split2(info_at(r1,c),   info_at(r1,c+1), ah[kt][1], al[kt][1]);
        split2(info_at(r0,c+8), info_at(r0,c+9), ah[kt][2], al[kt][2]);
        split2(info_at(r1,c+8), info_at(r1,c+9), ah[kt][3], al[kt][3]);
    }
    float pres00 = obs[(r0/NPREDD)*16 + 14], pres01 = obs[(r0/NPREDD)*16 + 15];
    float pres10 = obs[(r1/NPREDD)*16 + 14], pres11 = obs[(r1/NPREDD)*16 + 15];
    __syncthreads();

    for (int t = 0; t < FUTD; t++) {
        unsigned nh[6][4], nl[6][4];
        float f00 = 0.f, f01 = 0.f, f10 = 0.f, f11 = 0.f;

        #pragma unroll 1
        for (int g = 0; g < 12; g++) {
            float Cr[4] = {0,0,0,0}, Cz[4] = {0,0,0,0}, Cn[4] = {0,0,0,0};
            #pragma unroll
            for (int kt = 0; kt < 6; kt++) {
                unsigned a0 = ah[kt][0], a1 = ah[kt][1], a2 = ah[kt][2], a3 = ah[kt][3];
                unsigned b0 = al[kt][0], b1 = al[kt][1], b2 = al[kt][2], b3 = al[kt][3];
                #pragma unroll
                for (int gate = 0; gate < 3; gate++) {
                    int j = gate*96 + g*8 + gid;
                    int sw = ((j>>1)&3)*4;
                    int u0 = j*48 + ((kt*8+tg) ^ sw);
                    int u1 = j*48 + ((kt*8+4+tg) ^ sw);
                    unsigned bh0 = Wh32[u0], bh1 = Wh32[u1];
                    unsigned bl0 = Wl32[u0], bl1 = Wl32[u1];
                    float* C = (gate == 0) ? Cr : (gate == 1) ? Cz : Cn;
                    MMA_BF16(C, a0,a1,a2,a3, bh0,bh1);
                    MMA_BF16(C, a0,a1,a2,a3, bl0,bl1);
                    MMA_BF16(C, b0,b1,b2,b3, bh0,bh1);
                }
            }
            int d0 = g*8 + tg*2;
            float brz0 = sbrz[d0],    brz1 = sbrz[d0+1];
            float bz0  = sbrz[96+d0], bz1  = sbrz[96+d0+1];
            float bin0 = sbin[d0],    bin1 = sbin[d0+1];
            float bhn0 = sbhn[d0],    bhn1 = sbhn[d0+1];
            float rg0 = sg_(Cr[0]+brz0), rg1 = sg_(Cr[1]+brz1);
            float rg2 = sg_(Cr[2]+brz0), rg3 = sg_(Cr[3]+brz1);
            float z0 = sg_(Cz[0]+bz0), z1 = sg_(Cz[1]+bz1);
            float z2 = sg_(Cz[2]+bz0), z3 = sg_(Cz[3]+bz1);
            float h0, h1, h2, h3;
            if (t == 0) {
                h0 = (1.f-z0)*tanhf(Cn[0] + bin0 + rg0*bhn0);
                h1 = (1.f-z1)*tanhf(Cn[1] + bin1 + rg1*bhn1);
                h2 = (1.f-z2)*tanhf(Cn[2] + bin0 + rg2*bhn0);
                h3 = (1.f-z3)*tanhf(Cn[3] + bin1 + rg3*bhn1);
            } else {
                int kt = g >> 1, s0 = (g & 1)*2;
                unsigned uh0 = ah[kt][s0],   ul0 = al[kt][s0];
                unsigned uh1 = ah[kt][s0+1], ul1 = al[kt][s0+1];
                float ho0 = bflo(uh0) + bflo(ul0), ho1 = bfhi(uh0) + bfhi(ul0);
                float ho2 = bflo(uh1) + bflo(ul1), ho3 = bfhi(uh1) + bfhi(ul1);
                h0 = (1.f-z0)*tanhf(bin0 + rg0*(Cn[0]+bhn0)) + z0*ho0;
                h1 = (1.f-z1)*tanhf(bin1 + rg1*(Cn[1]+bhn1)) + z1*ho1;
                h2 = (1.f-z2)*tanhf(bin0 + rg2*(Cn[2]+bhn0)) + z2*ho2;
                h3 = (1.f-z3)*tanhf(bin1 + rg3*(Cn[3]+bhn1)) + z3*ho3;
            }
            int kt2 = g >> 1, s0 = (g & 1)*2;
            split2(h0, h1, nh[kt2][s0],   nl[kt2][s0]);
            split2(h2, h3, nh[kt2][s0+1], nl[kt2][s0+1]);
            float w00 = sfc[d0], w01 = sfc[d0+1], w10 = sfc[96+d0], w11 = sfc[96+d0+1];
            f00 = fmaf(h0, w00, fmaf(h1, w01, f00));
            f01 = fmaf(h0, w10, fmaf(h1, w11, f01));
            f10 = fmaf(h2, w00, fmaf(h3, w01, f10));
            f11 = fmaf(h2, w10, fmaf(h3, w11, f11));
        }
        #pragma unroll
        for (int kt = 0; kt < 6; kt++)
            #pragma unroll
            for (int e = 0; e < 4; e++) { ah[kt][e] = nh[kt][e]; al[kt][e] = nl[kt][e]; }

        f00 += __shfl_xor_sync(0xffffffffu, f00, 1);
        f00 += __shfl_xor_sync(0xffffffffu, f00, 2);
        f01 += __shfl_xor_sync(0xffffffffu, f01, 1);
        f01 += __shfl_xor_sync(0xffffffffu, f01, 2);
        f10 += __shfl_xor_sync(0xffffffffu, f10, 1);
        f10 += __shfl_xor_sync(0xffffffffu, f10, 2);
        f11 += __shfl_xor_sync(0xffffffffu, f11, 1);
        f11 += __shfl_xor_sync(0xffffffffu, f11, 2);
        pres00 += f00 + ((t==0) ? fcb[0] : fcb[0]);
        pres01 += f01 + fcb[1];
        pres10 += f10 + fcb[0];
        pres11 += f11 + fcb[1];
        // fix double-add form: fcb added once per step for each output (correct: pres += h@fc^T + fcb)
        if (tg == 0) {
            out[((size_t)r0*FUTD + t)*2 + 0] = pres00;
            out[((size_t)r0*FUTD + t)*2 + 1] = pres01;
            out[((size_t)r1*FUTD + t)*2 + 0] = pres10;
            out[((size_t)r1*FUTD + t)*2 + 1] = pres11;
        }
        if (t == 0) {
            __syncthreads();
            stageW(Wh32, Wl32, g_Whh_h, g_Whh_l, tid);
            __syncthreads();
        }
    }
}

extern "C" void kernel_launch(void* const* d_in, const int* in_sizes, int n_in,
                              void* d_out, int out_size)
{
    const float* past    = (const float*)d_in[0];
    const float* obs     = (const float*)d_in[1];
    const float* conv_w  = (const float*)d_in[2];
    const float* conv_b  = (const float*)d_in[3];
    const float* enc_wih = (const float*)d_in[4];
    const float* enc_whh = (const float*)d_in[5];
    const float* enc_bih = (const float*)d_in[6];
    const float* enc_bhh = (const float*)d_in[7];
    const float* mem_p   = (const float*)d_in[8];
    const float* mem_f   = (const float*)d_in[9];
    const float* Wq      = (const float*)d_in[10];
    const float* bq      = (const float*)d_in[11];
    const float* Wk      = (const float*)d_in[12];
    const float* bk      = (const float*)d_in[13];
    const float* Wv      = (const float*)d_in[14];
    const float* bv      = (const float*)d_in[15];
    const float* dec_wih = (const float*)d_in[16];
    const float* dec_whh = (const float*)d_in[17];
    const float* dec_bih = (const float*)d_in[18];
    const float* dec_bhh = (const float*)d_in[19];
    const float* fc_w    = (const float*)d_in[20];
    const float* fc_b    = (const float*)d_in[21];
    float* out = (float*)d_out;

    cudaFuncSetAttribute(attn_kernel,
        cudaFuncAttributeMaxDynamicSharedMemorySize, SMEM_ATTN);
    cudaFuncSetAttribute(dec_kernel,
        cudaFuncAttributeMaxDynamicSharedMemorySize, DEC_SMEM);

    enc_kernel<<<BD, 144>>>(past, conv_w, conv_b, enc_wih, enc_whh,
                            enc_bih, enc_bhh, Wq, bq);
    kproj_kernel<<<(MD*48 + 255)/256, 256>>>(mem_p, Wk, bk);
    vproj_kernel<<<MD/256, 256>>>(mem_f, Wv, bv);
    wsplit_kernel<<<(288*96 + 255)/256, 256>>>(dec_wih, dec_whh);

    for (int it = 0; it < NPREDD; it++) {
        attn_kernel<<<dim3(NSLICE, BD/64), 128, SMEM_ATTN>>>();
        combine_kernel<<<64, 384>>>(Wq, bq, it);
    }

    dec_kernel<<<NROWS/64, 128, DEC_SMEM>>>(obs, dec_bih, dec_bhh, fc_w, fc_b, out);
}

// round 13
// speedup vs baseline: 1.1984x; 1.0092x over previous
#include <cuda_runtime.h>
#include <cuda_bf16.h>
#include <math.h>

#define BD 512
#define MD 32768
#define NPREDD 20
#define FUTD 12
#define NROWS (BD*NPREDD)
#define NSLICE 54

// attn smem: 2 KV buffers + Q staging
#define KVBUF_B   28160
#define OFF_Q     (2*KVBUF_B)
#define SMEM_ATTN (OFF_Q + 64*48*4)

// decoder smem: W (hi+lo) swizzled + small bias/fc tables
#define DEC_W_BYTES (288*96*2*2)            // 110592
#define DEC_SMEM    (DEC_W_BYTES + 576*4)   // +2304 = 112896

__device__ float g_state[BD*48];
__device__ float g_q[BD*48];
__device__ __nv_bfloat16 g_Kh[MD*48];
__device__ __nv_bfloat16 g_Kl[MD*48];
__device__ __nv_bfloat16 g_Vth[48*MD];
__device__ __nv_bfloat16 g_Vtl[48*MD];
__device__ float g_part[NSLICE*BD*52];
__device__ float g_pred[NROWS*48];
__device__ __nv_bfloat16 g_Wih_h[288*96];
__device__ __nv_bfloat16 g_Wih_l[288*96];
__device__ __nv_bfloat16 g_Whh_h[288*96];
__device__ __nv_bfloat16 g_Whh_l[288*96];

__device__ __forceinline__ float sg_(float x){ return 1.f/(1.f+__expf(-x)); }

__device__ __forceinline__ void cpa16(void* dst, const void* src){
    unsigned ds = (unsigned)__cvta_generic_to_shared(dst);
    asm volatile("cp.async.cg.shared.global [%0], [%1], 16;\n" :: "r"(ds), "l"(src));
}

#define MMA_BF16(c, a0,a1,a2,a3, b0,b1) \
    asm volatile("mma.sync.aligned.m16n8k16.row.col.f32.bf16.bf16.f32 " \
        "{%0,%1,%2,%3}, {%4,%5,%6,%7}, {%8,%9}, {%0,%1,%2,%3};" \
        : "+f"(c[0]), "+f"(c[1]), "+f"(c[2]), "+f"(c[3]) \
        : "r"(a0),"r"(a1),"r"(a2),"r"(a3),"r"(b0),"r"(b1))

__device__ __forceinline__ unsigned ldu32(const __nv_bfloat16* p){
    return *(const unsigned*)p;
}
__device__ __forceinline__ unsigned short us_(__nv_bfloat16 h){
    return *(unsigned short*)&h;
}
__device__ __forceinline__ void split2(float a, float b, unsigned &hi, unsigned &lo){
    __nv_bfloat16 ha = __float2bfloat16(a), hb = __float2bfloat16(b);
    __nv_bfloat16 la = __float2bfloat16(a - __bfloat162float(ha));
    __nv_bfloat16 lb = __float2bfloat16(b - __bfloat162float(hb));
    hi = (unsigned)us_(ha) | ((unsigned)us_(hb) << 16);
    lo = (unsigned)us_(la) | ((unsigned)us_(lb) << 16);
}
__device__ __forceinline__ void splits(float v, __nv_bfloat16* ph, __nv_bfloat16* pl){
    __nv_bfloat16 h = __float2bfloat16(v);
    *ph = h;
    *pl = __float2bfloat16(v - __bfloat162float(h));
}
__device__ __forceinline__ float bflo(unsigned u){
    return __bfloat162float(__ushort_as_bfloat16((unsigned short)(u & 0xffffu)));
}
__device__ __forceinline__ float bfhi(unsigned u){
    return __bfloat162float(__ushort_as_bfloat16((unsigned short)(u >> 16)));
}

// ---------- encoder ----------
__global__ void enc_kernel(const float* __restrict__ past,
    const float* __restrict__ cw, const float* __restrict__ cb,
    const float* __restrict__ wih, const float* __restrict__ whh,
    const float* __restrict__ bih, const float* __restrict__ bhh,
    const float* __restrict__ Wq, const float* __restrict__ bq)
{
    __shared__ float se[8][48];
    __shared__ float sh[48];
    __shared__ float sgi[144], sgh[144];
    int b = blockIdx.x, tid = threadIdx.x;
    for (int idx = tid; idx < 8*48; idx += 144) {
        int t = idx/48, c = idx%48;
        float s = cb[c];
        #pragma unroll
        for (int k = 0; k < 3; k++) {
            int tt = t + k - 1;
            if (tt >= 0 && tt < 8) {
                s = fmaf(cw[c*6+k],   past[b*16+tt*2+0], s);
                s = fmaf(cw[c*6+3+k], past[b*16+tt*2+1], s);
            }
        }
        se[t][c] = fmaxf(s, 0.f);
    }
    if (tid < 48) sh[tid] = 0.f;
    __syncthreads();
    for (int t = 0; t < 8; t++) {
        float gi = bih[tid], gh = bhh[tid];
        const float* wi = wih + tid*48;
        const float* wh = whh + tid*48;
        #pragma unroll 8
        for (int d = 0; d < 48; d++) {
            gi = fmaf(se[t][d], wi[d], gi);
            gh = fmaf(sh[d],    wh[d], gh);
        }
        sgi[tid] = gi; sgh[tid] = gh;
        __syncthreads();
        float hn = 0.f;
        if (tid < 48) {
            float r = sg_(sgi[tid]    + sgh[tid]);
            float z = sg_(sgi[48+tid] + sgh[48+tid]);
            float n = tanhf(sgi[96+tid] + r*sgh[96+tid]);
            hn = (1.f-z)*n + z*sh[tid];
        }
        __syncthreads();
        if (tid < 48) sh[tid] = hn;
        __syncthreads();
    }
    if (tid < 48) {
        g_state[b*48+tid] = sh[tid];
        float q = bq[tid];
        const float* w = Wq + tid*48;
        #pragma unroll 8
        for (int d = 0; d < 48; d++) q = fmaf(sh[d], w[d], q);
        g_q[b*48+tid] = q;
    }
}

// ---------- K projection + hi/lo split (m-major) ----------
__global__ void kproj_kernel(const float* __restrict__ mp,
    const float* __restrict__ Wk, const float* __restrict__ bk)
{
    int idx = blockIdx.x*blockDim.x + threadIdx.x;
    if (idx >= MD*48) return;
    int m = idx/48, j = idx - m*48;
    const float* rp = mp + m*48;
    const float* wk = Wk + j*48;
    float sk = bk[j];
    #pragma unroll 8
    for (int d = 0; d < 48; d++) sk = fmaf(rp[d], wk[d], sk);
    splits(sk, &g_Kh[idx], &g_Kl[idx]);
}

// ---------- V projection + hi/lo split, transposed (d-major) ----------
__global__ void vproj_kernel(const float* __restrict__ mf,
    const float* __restrict__ Wv, const float* __restrict__ bv)
{
    __shared__ float sW[48*48];
    __shared__ float sb[48];
    int tid = threadIdx.x;
    for (int i = tid; i < 48*48; i += 256) sW[i] = Wv[i];
    if (tid < 48) sb[tid] = bv[tid];
    __syncthreads();
    int m = blockIdx.x*256 + tid;
    float r[48];
    #pragma unroll 8
    for (int d = 0; d < 48; d++) r[d] = mf[(size_t)m*48 + d];
    #pragma unroll 1
    for (int j = 0; j < 48; j++) {
        float sv = sb[j];
        const float* w = sW + j*48;
        #pragma unroll 8
        for (int d = 0; d < 48; d++) sv = fmaf(r[d], w[d], sv);
        splits(sv, &g_Vth[(size_t)j*MD + m], &g_Vtl[(size_t)j*MD + m]);
    }
}

// ---------- decoder weight hi/lo split (row-major [288][96]) ----------
__global__ void wsplit_kernel(const float* __restrict__ wih, const float* __restrict__ whh)
{
    int i = blockIdx.x*blockDim.x + threadIdx.x;
    if (i < 288*96) {
        splits(wih[i], &g_Wih_h[i], &g_Wih_l[i]);
        splits(whh[i], &g_Whh_h[i], &g_Whh_l[i]);
    }
}

// ---------- prefetch helper (attn) ----------
__device__ __forceinline__ void prefetch_chunk(char* base, int m0, int tid){
    #pragma unroll
    for (int i = tid; i < 768; i += 128) {
        int arr = i / 384;
        int r = (i % 384) / 6, seg = i % 6;
        const char* src = (const char*)(arr ? g_Kl : g_Kh) + ((size_t)(m0+r)*48)*2 + seg*16;
        cpa16(base + arr*7168 + r*112 + seg*16, src);
    }
    #pragma unroll
    for (int i = tid; i < 768; i += 128) {
        int arr = i / 384;
        int r = (i % 384) / 8, seg = i % 8;
        const char* src = (const char*)(arr ? g_Vtl : g_Vth) + ((size_t)r*MD + m0)*2 + seg*16;
        cpa16(base + 14336 + arr*6912 + r*144 + seg*16, src);
    }
}

// ---------- attention: register-resident FA2, bf16-split HMMA, 3 CTA/SM ----------
__global__ void __launch_bounds__(128,3) attn_kernel()
{
    extern __shared__ char sm[];
    int tid = threadIdx.x, lane = tid & 31, w = tid >> 5;
    int gid = lane >> 2, tg = lane & 3;
    int qbase = blockIdx.y * 64;
    int s = blockIdx.x;
    int m_start = (s < 26) ? s*640 : 16640 + (s-26)*576;
    int nch = (s < 26) ? 10 : 9;

    float* sQ = (float*)(sm + OFF_Q);
    for (int i = tid; i < 64*48; i += 128) sQ[i] = g_q[qbase*48 + i];
    __syncthreads();

    unsigned qh[3][4], ql[3][4];
    {
        int r0 = w*16 + gid, r1 = r0 + 8;
        #pragma unroll
        for (int j = 0; j < 3; j++) {
            int c = j*16 + tg*2;
            split2(sQ[r0*48 + c],     sQ[r0*48 + c + 1],     qh[j][0], ql[j][0]);
            split2(sQ[r1*48 + c],     sQ[r1*48 + c + 1],     qh[j][1], ql[j][1]);
            split2(sQ[r0*48 + c + 8], sQ[r0*48 + c + 9],     qh[j][2], ql[j][2]);
            split2(sQ[r1*48 + c + 8], sQ[r1*48 + c + 9],     qh[j][3], ql[j][3]);
        }
    }

    prefetch_chunk(sm, m_start, tid);
    asm volatile("cp.async.commit_group;\n");

    float O[6][4];
    #pragma unroll
    for (int dt = 0; dt < 6; dt++) { O[dt][0]=0.f; O[dt][1]=0.f; O[dt][2]=0.f; O[dt][3]=0.f; }
    float rm0 = -1e30f, rm1 = -1e30f, rs0 = 0.f, rs1 = 0.f;

    for (int c = 0; c < nch; c++) {
        asm volatile("cp.async.wait_group 0;\n" ::: "memory");
        __syncthreads();
        if (c + 1 < nch)
            prefetch_chunk(sm + ((c+1)&1)*KVBUF_B, m_start + (c+1)*64, tid);
        asm volatile("cp.async.commit_group;\n");

        const __nv_bfloat16* Kh = (const __nv_bfloat16*)(sm + (c&1)*KVBUF_B);
        const __nv_bfloat16* Kl = Kh + 64*56;
        const __nv_bfloat16* Vh = (const __nv_bfloat16*)(sm + (c&1)*KVBUF_B + 14336);
        const __nv_bfloat16* Vl = Vh + 48*72;

        float Sc[8][4];
        #pragma unroll
        for (int nt = 0; nt < 8; nt++) { Sc[nt][0]=0.f; Sc[nt][1]=0.f; Sc[nt][2]=0.f; Sc[nt][3]=0.f; }
        #pragma unroll
        for (int j = 0; j < 3; j++) {
            int kc = j*16 + tg*2;
            #pragma unroll
            for (int nt = 0; nt < 8; nt++) {
                const __nv_bfloat16* kr = Kh + (nt*8+gid)*56 + kc;
                const __nv_bfloat16* lr = Kl + (nt*8+gid)*56 + kc;
                unsigned kh0 = ldu32(kr), kh1 = ldu32(kr + 8);
                unsigned kl0 = ldu32(lr), kl1 = ldu32(lr + 8);
                MMA_BF16(Sc[nt], qh[j][0],qh[j][1],qh[j][2],qh[j][3], kh0,kh1);
                MMA_BF16(Sc[nt], qh[j][0],qh[j][1],qh[j][2],qh[j][3], kl0,kl1);
                MMA_BF16(Sc[nt], ql[j][0],ql[j][1],ql[j][2],ql[j][3], kh0,kh1);
            }
        }

        float m0 = Sc[0][0], m1 = Sc[0][2];
        #pragma unroll
        for (int nt = 0; nt < 8; nt++) {
            m0 = fmaxf(m0, fmaxf(Sc[nt][0], Sc[nt][1]));
            m1 = fmaxf(m1, fmaxf(Sc[nt][2], Sc[nt][3]));
        }
        m0 = fmaxf(m0, __shfl_xor_sync(0xffffffffu, m0, 1));
        m0 = fmaxf(m0, __shfl_xor_sync(0xffffffffu, m0, 2));
        m1 = fmaxf(m1, __shfl_xor_sync(0xffffffffu, m1, 1));
        m1 = fmaxf(m1, __shfl_xor_sync(0xffffffffu, m1, 2));
        float nm0 = fmaxf(rm0, m0), nm1 = fmaxf(rm1, m1);
        float f0 = __expf(rm0 - nm0), f1 = __expf(rm1 - nm1);
        rm0 = nm0; rm1 = nm1;
        rs0 *= f0; rs1 *= f1;
        #pragma unroll
        for (int dt = 0; dt < 6; dt++) {
            O[dt][0] *= f0; O[dt][1] *= f0;
            O[dt][2] *= f1; O[dt][3] *= f1;
        }

        #pragma unroll
        for (int half = 0; half < 2; half++) {
            unsigned p01h[4], p01l[4], p23h[4], p23l[4];
            #pragma unroll
            for (int k = 0; k < 4; k++) {
                int nt = half*4 + k;
                float p0 = __expf(Sc[nt][0] - nm0);
                float p1 = __expf(Sc[nt][1] - nm0);
                float p2 = __expf(Sc[nt][2] - nm1);
                float p3 = __expf(Sc[nt][3] - nm1);
                rs0 += p0 + p1; rs1 += p2 + p3;
                split2(p0, p1, p01h[k], p01l[k]);
                split2(p2, p3, p23h[k], p23l[k]);
            }
            #pragma unroll
            for (int tt = 0; tt < 2; tt++) {
                int t = half*2 + tt;
                unsigned ah0 = p01h[2*tt],   ah1 = p23h[2*tt];
                unsigned ah2 = p01h[2*tt+1], ah3 = p23h[2*tt+1];
                unsigned al0 = p01l[2*tt],   al1 = p23l[2*tt];
                unsigned al2 = p01l[2*tt+1], al3 = p23l[2*tt+1];
                int mk = t*16 + tg*2;
                #pragma unroll
                for (int dt = 0; dt < 6; dt++) {
                    const __nv_bfloat16* vr = Vh + (dt*8+gid)*72 + mk;
                    const __nv_bfloat16* wr = Vl + (dt*8+gid)*72 + mk;
                    unsigned vh0 = ldu32(vr), vh1 = ldu32(vr + 8);
                    unsigned vl0 = ldu32(wr), vl1 = ldu32(wr + 8);
                    MMA_BF16(O[dt], ah0,ah1,ah2,ah3, vh0,vh1);
                    MMA_BF16(O[dt], ah0,ah1,ah2,ah3, vl0,vl1);
                    MMA_BF16(O[dt], al0,al1,al2,al3, vh0,vh1);
                }
            }
        }
    }

    rs0 += __shfl_xor_sync(0xffffffffu, rs0, 1);
    rs0 += __shfl_xor_sync(0xffffffffu, rs0, 2);
    rs1 += __shfl_xor_sync(0xffffffffu, rs1, 1);
    rs1 += __shfl_xor_sync(0xffffffffu, rs1, 2);

    int gq0 = qbase + w*16 + gid, gq1 = gq0 + 8;
    float* P0 = g_part + ((size_t)s*BD + gq0)*52;
    float* P1 = g_part + ((size_t)s*BD + gq1)*52;
    #pragma unroll
    for (int dt = 0; dt < 6; dt++) {
        int col = dt*8 + tg*2;
        P0[col]   = O[dt][0];
        P0[col+1] = O[dt][1];
        P1[col]   = O[dt][2];
        P1[col+1] = O[dt][3];
    }
    if (tg == 0) {
        P0[48] = rm0; P0[49] = rs0;
        P1[48] = rm1; P1[49] = rs1;
    }
}

// ---------- combine partials + emit pred + next q (8 q per block) ----------
__global__ void combine_kernel(const float* __restrict__ Wq, const float* __restrict__ bq,
                               int iter)
{
    __shared__ float sc[8][48];
    int t = threadIdx.x;
    int ql = t / 48, d = t - ql*48;
    int q = blockIdx.x*8 + ql;
    float gm = -1e30f;
    #pragma unroll 6
    for (int s = 0; s < NSLICE; s++)
        gm = fmaxf(gm, g_part[((size_t)s*BD+q)*52 + 48]);
    float tot = 0.f, av = 0.f;
    #pragma unroll 6
    for (int s = 0; s < NSLICE; s++) {
        const float* P = g_part + ((size_t)s*BD+q)*52;
        float e = __expf(P[48] - gm);
        tot = fmaf(P[49], e, tot);
        av  = fmaf(P[d],  e, av);
    }
    float att = av / tot;
    g_pred[(q*NPREDD + iter)*48 + d] = att;
    sc[ql][d] = g_q[q*48+d] + att;
    __syncthreads();
    float qn = bq[d];
    const float* w = Wq + d*48;
    #pragma unroll 8
    for (int k = 0; k < 48; k++) qn = fmaf(sc[ql][k], w[k], qn);
    g_q[q*48+d] = qn;
}

// ---------- decoder: register-resident HMMA GRU, 64 rows/CTA ----------
__device__ __forceinline__ float info_at(int n, int d){
    return (d < 48) ? g_state[(n/NPREDD)*48 + d] : g_pred[(size_t)n*48 + (d-48)];
}
__device__ __forceinline__ void stageW(unsigned* Wh32, unsigned* Wl32,
    const __nv_bfloat16* gh, const __nv_bfloat16* gl, int tid)
{
    const unsigned* sh = (const unsigned*)gh;
    const unsigned* sl = (const unsigned*)gl;
    for (int i = tid; i < 288*48; i += 128) {
        int j = i / 48, kk = i - j*48;
        int u = j*48 + (kk ^ (((j>>1)&3)*4));
        Wh32[u] = sh[i];
        Wl32[u] = sl[i];
    }
}

__global__ void __launch_bounds__(128,2) dec_kernel(
    const float* __restrict__ obs,
    const float* __restrict__ bih, const float* __restrict__ bhh,
    const float* __restrict__ fcw, const float* __restrict__ fcb,
    float* __restrict__ out)
{
    extern __shared__ char dsm[];
    unsigned* Wh32 = (unsigned*)dsm;
    unsigned* Wl32 = Wh32 + 288*48;
    float* sbrz = (float*)(dsm + DEC_W_BYTES);
    float* sbin = sbrz + 192;
    float* sbhn = sbin + 96;
    float* sfc  = sbhn + 96;

    int tid = threadIdx.x, lane = tid & 31, w = tid >> 5;
    int gid = lane >> 2, tg = lane & 3;
    int nbase = blockIdx.x*64;
    int r0 = nbase + w*16 + gid, r1 = r0 + 8;

    for (int i = tid; i < 192; i += 128) { sbrz[i] = bih[i] + bhh[i]; sfc[i] = fcw[i]; }
    for (int i = tid; i < 96; i += 128)  { sbin[i] = bih[192+i]; sbhn[i] = bhh[192+i]; }
    stageW(Wh32, Wl32, g_Wih_h, g_Wih_l, tid);

    unsigned ah[6][4], al[6][4];
    #pragma unroll
    for (int kt = 0; kt < 6; kt++) {
        int c = kt*16 + tg*2;
        split2(info_at(r0,c),   info_at(r0,c+1), ah[kt][0], al[kt][0]);
        split2(info_at(r1,c),   info_at(r1,c+1), ah[kt][1], al[kt][1]);
        split2(info_at(r0,c+8), info_at(r0,c+9), ah[kt][2], al[kt][2]);
        split2(info_at(r1,c+8), info_at(r1,c+9), ah[kt][3], al[kt][3]);
    }
    float pres00 = obs[(r0/NPREDD)*16 + 14], pres01 = obs[(r0/NPREDD)*16 + 15];
    float pres10 = obs[(r1/NPREDD)*16 + 14], pres11 = obs[(r1/NPREDD)*16 + 15];
    __syncthreads();

    for (int t = 0; t < FUTD; t++) {
        unsigned nh[6][4], nl[6][4];
        float f00 = 0.f, f01 = 0.f, f10 = 0.f, f11 = 0.f;

        #pragma unroll 1
        for (int g = 0; g < 12; g++) {
            float Cr[4] = {0,0,0,0}, Cz[4] = {0,0,0,0}, Cn[4] = {0,0,0,0};
            #pragma unroll
            for (int kt = 0; kt < 6; kt++) {
                unsigned a0 = ah[kt][0], a1 = ah[kt][1], a2 = ah[kt][2], a3 = ah[kt][3];
                unsigned b0 = al[kt][0], b1 = al[kt][1], b2 = al[kt][2], b3 = al[kt][3];
                #pragma unroll
                for (int gate = 0; gate < 3; gate++) {
                    int j = gate*96 + g*8 + gid;
                    int sw = ((j>>1)&3)*4;
                    int u0 = j*48 + ((kt*8+tg) ^ sw);
                    int u1 = j*48 + ((kt*8+4+tg) ^ sw);
                    unsigned bh0 = Wh32[u0], bh1 = Wh32[u1];
                    unsigned bl0 = Wl32[u0], bl1 = Wl32[u1];
                    float* C = (gate == 0) ? Cr : (gate == 1) ? Cz : Cn;
                    MMA_BF16(C, a0,a1,a2,a3, bh0,bh1);
                    MMA_BF16(C, a0,a1,a2,a3, bl0,bl1);
                    MMA_BF16(C, b0,b1,b2,b3, bh0,bh1);
                }
            }
            int d0 = g*8 + tg*2;
            float brz0 = sbrz[d0],    brz1 = sbrz[d0+1];
            float bz0  = sbrz[96+d0], bz1  = sbrz[96+d0+1];
            float bin0 = sbin[d0],    bin1 = sbin[d0+1];
            float bhn0 = sbhn[d0],    bhn1 = sbhn[d0+1];
            float rg0 = sg_(Cr[0]+brz0), rg1 = sg_(Cr[1]+brz1);
            float rg2 = sg_(Cr[2]+brz0), rg3 = sg_(Cr[3]+brz1);
            float z0 = sg_(Cz[0]+bz0), z1 = sg_(Cz[1]+bz1);
            float z2 = sg_(Cz[2]+bz0), z3 = sg_(Cz[3]+bz1);
            float h0, h1, h2, h3;
            if (t == 0) {
                h0 = (1.f-z0)*tanhf(Cn[0] + bin0 + rg0*bhn0);
                h1 = (1.f-z1)*tanhf(Cn[1] + bin1 + rg1*bhn1);
                h2 = (1.f-z2)*tanhf(Cn[2] + bin0 + rg2*bhn0);
                h3 = (1.f-z3)*tanhf(Cn[3] + bin1 + rg3*bhn1);
            } else {
                int kt = g >> 1, s0 = (g & 1)*2;
                unsigned uh0 = ah[kt][s0],   ul0 = al[kt][s0];
                unsigned uh1 = ah[kt][s0+1], ul1 = al[kt][s0+1];
                float ho0 = bflo(uh0) + bflo(ul0), ho1 = bfhi(uh0) + bfhi(ul0);
                float ho2 = bflo(uh1) + bflo(ul1), ho3 = bfhi(uh1) + bfhi(ul1);
                h0 = (1.f-z0)*tanhf(bin0 + rg0*(Cn[0]+bhn0)) + z0*ho0;
                h1 = (1.f-z1)*tanhf(bin1 + rg1*(Cn[1]+bhn1)) + z1*ho1;
                h2 = (1.f-z2)*tanhf(bin0 + rg2*(Cn[2]+bhn0)) + z2*ho2;
                h3 = (1.f-z3)*tanhf(bin1 + rg3*(Cn[3]+bhn1)) + z3*ho3;
            }
            int kt2 = g >> 1, s0 = (g & 1)*2;
            split2(h0, h1, nh[kt2][s0],   nl[kt2][s0]);
            split2(h2, h3, nh[kt2][s0+1], nl[kt2][s0+1]);
            float w00 = sfc[d0], w01 = sfc[d0+1], w10 = sfc[96+d0], w11 = sfc[96+d0+1];
            f00 = fmaf(h0, w00, fmaf(h1, w01, f00));
            f01 = fmaf(h0, w10, fmaf(h1, w11, f01));
            f10 = fmaf(h2, w00, fmaf(h3, w01, f10));
            f11 = fmaf(h2, w10, fmaf(h3, w11, f11));
        }
        #pragma unroll
        for (int kt = 0; kt < 6; kt++)
            #pragma unroll
            for (int e = 0; e < 4; e++) { ah[kt][e] = nh[kt][e]; al[kt][e] = nl[kt][e]; }

        f00 += __shfl_xor_sync(0xffffffffu, f00, 1);
        f00 += __shfl_xor_sync(0xffffffffu, f00, 2);
        f01 += __shfl_xor_sync(0xffffffffu, f01, 1);
        f01 += __shfl_xor_sync(0xffffffffu, f01, 2);
        f10 += __shfl_xor_sync(0xffffffffu, f10, 1);
        f10 += __shfl_xor_sync(0xffffffffu, f10, 2);
        f11 += __shfl_xor_sync(0xffffffffu, f11, 1);
        f11 += __shfl_xor_sync(0xffffffffu, f11, 2);
        pres00 += f00 + fcb[0];
        pres01 += f01 + fcb[1];
        pres10 += f10 + fcb[0];
        pres11 += f11 + fcb[1];
        if (tg == 0) {
            out[((size_t)r0*FUTD + t)*2 + 0] = pres00;
            out[((size_t)r0*FUTD + t)*2 + 1] = pres01;
            out[((size_t)r1*FUTD + t)*2 + 0] = pres10;
            out[((size_t)r1*FUTD + t)*2 + 1] = pres11;
        }
        if (t == 0) {
            __syncthreads();
            stageW(Wh32, Wl32, g_Whh_h, g_Whh_l, tid);
            __syncthreads();
        }
    }
}

extern "C" void kernel_launch(void* const* d_in, const int* in_sizes, int n_in,
                              void* d_out, int out_size)
{
    const float* past    = (const float*)d_in[0];
    const float* obs     = (const float*)d_in[1];
    const float* conv_w  = (const float*)d_in[2];
    const float* conv_b  = (const float*)d_in[3];
    const float* enc_wih = (const float*)d_in[4];
    const float* enc_whh = (const float*)d_in[5];
    const float* enc_bih = (const float*)d_in[6];
    const float* enc_bhh = (const float*)d_in[7];
    const float* mem_p   = (const float*)d_in[8];
    const float* mem_f   = (const float*)d_in[9];
    const float* Wq      = (const float*)d_in[10];
    const float* bq      = (const float*)d_in[11];
    const float* Wk      = (const float*)d_in[12];
    const float* bk      = (const float*)d_in[13];
    const float* Wv      = (const float*)d_in[14];
    const float* bv      = (const float*)d_in[15];
    const float* dec_wih = (const float*)d_in[16];
    const float* dec_whh = (const float*)d_in[17];
    const float* dec_bih = (const float*)d_in[18];
    const float* dec_bhh = (const float*)d_in[19];
    const float* fc_w    = (const float*)d_in[20];
    const float* fc_b    = (const float*)d_in[21];
    float* out = (float*)d_out;

    cudaFuncSetAttribute(attn_kernel,
        cudaFuncAttributeMaxDynamicSharedMemorySize, SMEM_ATTN);
    cudaFuncSetAttribute(dec_kernel,
        cudaFuncAttributeMaxDynamicSharedMemorySize, DEC_SMEM);

    enc_kernel<<<BD, 144>>>(past, conv_w, conv_b, enc_wih, enc_whh,
                            enc_bih, enc_bhh, Wq, bq);
    kproj_kernel<<<(MD*48 + 255)/256, 256>>>(mem_p, Wk, bk);
    vproj_kernel<<<MD/256, 256>>>(mem_f, Wv, bv);
    wsplit_kernel<<<(288*96 + 255)/256, 256>>>(dec_wih, dec_whh);

    for (int it = 0; it < NPREDD; it++) {
        attn_kernel<<<dim3(NSLICE, BD/64), 128, SMEM_ATTN>>>();
        combine_kernel<<<64, 384>>>(Wq, bq, it);
    }

    dec_kernel<<<NROWS/64, 128, DEC_SMEM>>>(obs, dec_bih, dec_bhh, fc_w, fc_b, out);
}

// round 15
// speedup vs baseline: 1.3710x; 1.1440x over previous
#include <cuda_runtime.h>
#include <cuda_bf16.h>
#include <cuda_fp16.h>
#include <math.h>

#define BD 512
#define MD 32768
#define NPREDD 20
#define FUTD 12
#define NROWS (BD*NPREDD)
#define NSLICE 54

// attn smem: 2 KV buffers (K [64][56] half = 7168B, V [48][72] half = 6912B) + Q staging
#define KVBUF_B   14336
#define OFF_Q     (2*KVBUF_B)
#define SMEM_ATTN (OFF_Q + 64*48*4)

// decoder smem: W (hi+lo bf16) swizzled + small bias/fc tables
#define DEC_W_BYTES (288*96*2*2)
#define DEC_SMEM    (DEC_W_BYTES + 576*4)

__device__ float g_state[BD*48];
__device__ float g_q[BD*48];
__device__ __half g_K[MD*48];          // fp16 hi only
__device__ __half g_Vt[48*MD];         // fp16 hi only, d-major
__device__ float g_part[NSLICE*BD*52];
__device__ float g_pred[NROWS*48];
__device__ __nv_bfloat16 g_Wih_h[288*96];
__device__ __nv_bfloat16 g_Wih_l[288*96];
__device__ __nv_bfloat16 g_Whh_h[288*96];
__device__ __nv_bfloat16 g_Whh_l[288*96];

__device__ __forceinline__ float sg_(float x){ return 1.f/(1.f+__expf(-x)); }

__device__ __forceinline__ void cpa16(void* dst, const void* src){
    unsigned ds = (unsigned)__cvta_generic_to_shared(dst);
    asm volatile("cp.async.cg.shared.global [%0], [%1], 16;\n" :: "r"(ds), "l"(src));
}

#define MMA_BF16(c, a0,a1,a2,a3, b0,b1) \
    asm volatile("mma.sync.aligned.m16n8k16.row.col.f32.bf16.bf16.f32 " \
        "{%0,%1,%2,%3}, {%4,%5,%6,%7}, {%8,%9}, {%0,%1,%2,%3};" \
        : "+f"(c[0]), "+f"(c[1]), "+f"(c[2]), "+f"(c[3]) \
        : "r"(a0),"r"(a1),"r"(a2),"r"(a3),"r"(b0),"r"(b1))

#define MMA_F16(c, a0,a1,a2,a3, b0,b1) \
    asm volatile("mma.sync.aligned.m16n8k16.row.col.f32.f16.f16.f32 " \
        "{%0,%1,%2,%3}, {%4,%5,%6,%7}, {%8,%9}, {%0,%1,%2,%3};" \
        : "+f"(c[0]), "+f"(c[1]), "+f"(c[2]), "+f"(c[3]) \
        : "r"(a0),"r"(a1),"r"(a2),"r"(a3),"r"(b0),"r"(b1))

__device__ __forceinline__ unsigned ldu32(const __nv_bfloat16* p){ return *(const unsigned*)p; }
__device__ __forceinline__ unsigned ldu32h(const __half* p){ return *(const unsigned*)p; }
__device__ __forceinline__ unsigned short us_(__nv_bfloat16 h){ return *(unsigned short*)&h; }
__device__ __forceinline__ unsigned short ush_(__half h){ return *(unsigned short*)&h; }

// bf16 hi/lo split (decoder path)
__device__ __forceinline__ void split2(float a, float b, unsigned &hi, unsigned &lo){
    __nv_bfloat16 ha = __float2bfloat16(a), hb = __float2bfloat16(b);
    __nv_bfloat16 la = __float2bfloat16(a - __bfloat162float(ha));
    __nv_bfloat16 lb = __float2bfloat16(b - __bfloat162float(hb));
    hi = (unsigned)us_(ha) | ((unsigned)us_(hb) << 16);
    lo = (unsigned)us_(la) | ((unsigned)us_(lb) << 16);
}
__device__ __forceinline__ void splits(float v, __nv_bfloat16* ph, __nv_bfloat16* pl){
    __nv_bfloat16 h = __float2bfloat16(v);
    *ph = h;
    *pl = __float2bfloat16(v - __bfloat162float(h));
}
// fp16 hi/lo split (attention path)
__device__ __forceinline__ void split2h(float a, float b, unsigned &hi, unsigned &lo){
    __half ha = __float2half_rn(a), hb = __float2half_rn(b);
    __half la = __float2half_rn(a - __half2float(ha));
    __half lb = __float2half_rn(b - __half2float(hb));
    hi = (unsigned)ush_(ha) | ((unsigned)ush_(hb) << 16);
    lo = (unsigned)ush_(la) | ((unsigned)ush_(lb) << 16);
}
__device__ __forceinline__ float bflo(unsigned u){
    return __bfloat162float(__ushort_as_bfloat16((unsigned short)(u & 0xffffu)));
}
__device__ __forceinline__ float bfhi(unsigned u){
    return __bfloat162float(__ushort_as_bfloat16((unsigned short)(u >> 16)));
}

// ---------- encoder ----------
__global__ void enc_kernel(const float* __restrict__ past,
    const float* __restrict__ cw, const float* __restrict__ cb,
    const float* __restrict__ wih, const float* __restrict__ whh,
    const float* __restrict__ bih, const float* __restrict__ bhh,
    const float* __restrict__ Wq, const float* __restrict__ bq)
{
    __shared__ float se[8][48];
    __shared__ float sh[48];
    __shared__ float sgi[144], sgh[144];
    int b = blockIdx.x, tid = threadIdx.x;
    for (int idx = tid; idx < 8*48; idx += 144) {
        int t = idx/48, c = idx%48;
        float s = cb[c];
        #pragma unroll
        for (int k = 0; k < 3; k++) {
            int tt = t + k - 1;
            if (tt >= 0 && tt < 8) {
                s = fmaf(cw[c*6+k],   past[b*16+tt*2+0], s);
                s = fmaf(cw[c*6+3+k], past[b*16+tt*2+1], s);
            }
        }
        se[t][c] = fmaxf(s, 0.f);
    }
    if (tid < 48) sh[tid] = 0.f;
    __syncthreads();
    for (int t = 0; t < 8; t++) {
        float gi = bih[tid], gh = bhh[tid];
        const float* wi = wih + tid*48;
        const float* wh = whh + tid*48;
        #pragma unroll 8
        for (int d = 0; d < 48; d++) {
            gi = fmaf(se[t][d], wi[d], gi);
            gh = fmaf(sh[d],    wh[d], gh);
        }
        sgi[tid] = gi; sgh[tid] = gh;
        __syncthreads();
        float hn = 0.f;
        if (tid < 48) {
            float r = sg_(sgi[tid]    + sgh[tid]);
            float z = sg_(sgi[48+tid] + sgh[48+tid]);
            float n = tanhf(sgi[96+tid] + r*sgh[96+tid]);
            hn = (1.f-z)*n + z*sh[tid];
        }
        __syncthreads();
        if (tid < 48) sh[tid] = hn;
        __syncthreads();
    }
    if (tid < 48) {
        g_state[b*48+tid] = sh[tid];
        float q = bq[tid];
        const float* w = Wq + tid*48;
        #pragma unroll 8
        for (int d = 0; d < 48; d++) q = fmaf(sh[d], w[d], q);
        g_q[b*48+tid] = q;
    }
}

// ---------- K projection (fp16 hi only, m-major) ----------
__global__ void kproj_kernel(const float* __restrict__ mp,
    const float* __restrict__ Wk, const float* __restrict__ bk)
{
    int idx = blockIdx.x*blockDim.x + threadIdx.x;
    if (idx >= MD*48) return;
    int m = idx/48, j = idx - m*48;
    const float* rp = mp + m*48;
    const float* wk = Wk + j*48;
    float sk = bk[j];
    #pragma unroll 8
    for (int d = 0; d < 48; d++) sk = fmaf(rp[d], wk[d], sk);
    g_K[idx] = __float2half_rn(sk);
}

// ---------- V projection (fp16 hi only, transposed d-major) ----------
__global__ void vproj_kernel(const float* __restrict__ mf,
    const float* __restrict__ Wv, const float* __restrict__ bv)
{
    __shared__ float sW[48*48];
    __shared__ float sb[48];
    int tid = threadIdx.x;
    for (int i = tid; i < 48*48; i += 256) sW[i] = Wv[i];
    if (tid < 48) sb[tid] = bv[tid];
    __syncthreads();
    int m = blockIdx.x*256 + tid;
    float r[48];
    #pragma unroll 8
    for (int d = 0; d < 48; d++) r[d] = mf[(size_t)m*48 + d];
    #pragma unroll 1
    for (int j = 0; j < 48; j++) {
        float sv = sb[j];
        const float* w = sW + j*48;
        #pragma unroll 8
        for (int d = 0; d < 48; d++) sv = fmaf(r[d], w[d], sv);
        g_Vt[(size_t)j*MD + m] = __float2half_rn(sv);
    }
}

// ---------- decoder weight hi/lo split (bf16) ----------
__global__ void wsplit_kernel(const float* __restrict__ wih, const float* __restrict__ whh)
{
    int i = blockIdx.x*blockDim.x + threadIdx.x;
    if (i < 288*96) {
        splits(wih[i], &g_Wih_h[i], &g_Wih_l[i]);
        splits(whh[i], &g_Whh_h[i], &g_Whh_l[i]);
    }
}

// ---------- prefetch helper (attn): K rows 96B, V rows 128B ----------
__device__ __forceinline__ void prefetch_chunk(char* base, int m0, int tid){
    #pragma unroll
    for (int i = tid; i < 384; i += 128) {
        int r = i/6, seg = i - (i/6)*6;
        cpa16(base + r*112 + seg*16,
              (const char*)g_K + (size_t)(m0+r)*96 + seg*16);
    }
    #pragma unroll
    for (int i = tid; i < 384; i += 128) {
        int r = i >> 3, seg = i & 7;
        cpa16(base + 7168 + r*144 + seg*16,
              (const char*)g_Vt + ((size_t)r*MD + m0)*2 + seg*16);
    }
}

// ---------- attention: register-resident FA2, fp16 2-term HMMA, 3 CTA/SM ----------
__global__ void __launch_bounds__(128,3) attn_kernel()
{
    extern __shared__ char sm[];
    int tid = threadIdx.x, lane = tid & 31, w = tid >> 5;
    int gid = lane >> 2, tg = lane & 3;
    int qbase = blockIdx.y * 64;
    int s = blockIdx.x;
    int m_start = (s < 26) ? s*640 : 16640 + (s-26)*576;
    int nch = (s < 26) ? 10 : 9;

    float* sQ = (float*)(sm + OFF_Q);
    for (int i = tid; i < 64*48; i += 128) sQ[i] = g_q[qbase*48 + i];
    __syncthreads();

    unsigned qh[3][4], ql[3][4];
    {
        int r0 = w*16 + gid, r1 = r0 + 8;
        #pragma unroll
        for (int j = 0; j < 3; j++) {
            int c = j*16 + tg*2;
            split2h(sQ[r0*48 + c],     sQ[r0*48 + c + 1],     qh[j][0], ql[j][0]);
            split2h(sQ[r1*48 + c],     sQ[r1*48 + c + 1],     qh[j][1], ql[j][1]);
            split2h(sQ[r0*48 + c + 8], sQ[r0*48 + c + 9],     qh[j][2], ql[j][2]);
            split2h(sQ[r1*48 + c + 8], sQ[r1*48 + c + 9],     qh[j][3], ql[j][3]);
        }
    }

    prefetch_chunk(sm, m_start, tid);
    asm volatile("cp.async.commit_group;\n");

    float O[6][4];
    #pragma unroll
    for (int dt = 0; dt < 6; dt++) { O[dt][0]=0.f; O[dt][1]=0.f; O[dt][2]=0.f; O[dt][3]=0.f; }
    float rm0 = -1e30f, rm1 = -1e30f, rs0 = 0.f, rs1 = 0.f;

    for (int c = 0; c < nch; c++) {
        asm volatile("cp.async.wait_group 0;\n" ::: "memory");
        __syncthreads();
        if (c + 1 < nch)
            prefetch_chunk(sm + ((c+1)&1)*KVBUF_B, m_start + (c+1)*64, tid);
        asm volatile("cp.async.commit_group;\n");

        const __half* K = (const __half*)(sm + (c&1)*KVBUF_B);
        const __half* V = (const __half*)(sm + (c&1)*KVBUF_B + 7168);

        // ---- QK^T: 2 MMAs per tile (qh·k, ql·k) ----
        float Sc[8][4];
        #pragma unroll
        for (int nt = 0; nt < 8; nt++) { Sc[nt][0]=0.f; Sc[nt][1]=0.f; Sc[nt][2]=0.f; Sc[nt][3]=0.f; }
        #pragma unroll
        for (int j = 0; j < 3; j++) {
            int kc = j*16 + tg*2;
            #pragma unroll
            for (int nt = 0; nt < 8; nt++) {
                const __half* kr = K + (nt*8+gid)*56 + kc;
                unsigned k0 = ldu32h(kr), k1 = ldu32h(kr + 8);
                MMA_F16(Sc[nt], qh[j][0],qh[j][1],qh[j][2],qh[j][3], k0,k1);
                MMA_F16(Sc[nt], ql[j][0],ql[j][1],ql[j][2],ql[j][3], k0,k1);
            }
        }

        // ---- online softmax (row = 4 lanes of a quad) ----
        float m0 = Sc[0][0], m1 = Sc[0][2];
        #pragma unroll
        for (int nt = 0; nt < 8; nt++) {
            m0 = fmaxf(m0, fmaxf(Sc[nt][0], Sc[nt][1]));
            m1 = fmaxf(m1, fmaxf(Sc[nt][2], Sc[nt][3]));
        }
        m0 = fmaxf(m0, __shfl_xor_sync(0xffffffffu, m0, 1));
        m0 = fmaxf(m0, __shfl_xor_sync(0xffffffffu, m0, 2));
        m1 = fmaxf(m1, __shfl_xor_sync(0xffffffffu, m1, 1));
        m1 = fmaxf(m1, __shfl_xor_sync(0xffffffffu, m1, 2));
        float nm0 = fmaxf(rm0, m0), nm1 = fmaxf(rm1, m1);
        float f0 = __expf(rm0 - nm0), f1 = __expf(rm1 - nm1);
        rm0 = nm0; rm1 = nm1;
        rs0 *= f0; rs1 *= f1;
        #pragma unroll
        for (int dt = 0; dt < 6; dt++) {
            O[dt][0] *= f0; O[dt][1] *= f0;
            O[dt][2] *= f1; O[dt][3] *= f1;
        }

        // ---- exp + PV in two halves: 2 MMAs per tile (ph·v, pl·v) ----
        #pragma unroll
        for (int half = 0; half < 2; half++) {
            unsigned p01h[4], p01l[4], p23h[4], p23l[4];
            #pragma unroll
            for (int k = 0; k < 4; k++) {
                int nt = half*4 + k;
                float p0 = __expf(Sc[nt][0] - nm0);
                float p1 = __expf(Sc[nt][1] - nm0);
                float p2 = __expf(Sc[nt][2] - nm1);
                float p3 = __expf(Sc[nt][3] - nm1);
                rs0 += p0 + p1; rs1 += p2 + p3;
                split2h(p0, p1, p01h[k], p01l[k]);
                split2h(p2, p3, p23h[k], p23l[k]);
            }
            #pragma unroll
            for (int tt = 0; tt < 2; tt++) {
                int t = half*2 + tt;
                unsigned ah0 = p01h[2*tt],   ah1 = p23h[2*tt];
                unsigned ah2 = p01h[2*tt+1], ah3 = p23h[2*tt+1];
                unsigned al0 = p01l[2*tt],   al1 = p23l[2*tt];
                unsigned al2 = p01l[2*tt+1], al3 = p23l[2*tt+1];
                int mk = t*16 + tg*2;
                #pragma unroll
                for (int dt = 0; dt < 6; dt++) {
                    const __half* vr = V + (dt*8+gid)*72 + mk;
                    unsigned v0 = ldu32h(vr), v1 = ldu32h(vr + 8);
                    MMA_F16(O[dt], ah0,ah1,ah2,ah3, v0,v1);
                    MMA_F16(O[dt], al0,al1,al2,al3, v0,v1);
                }
            }
        }
    }

    rs0 += __shfl_xor_sync(0xffffffffu, rs0, 1);
    rs0 += __shfl_xor_sync(0xffffffffu, rs0, 2);
    rs1 += __shfl_xor_sync(0xffffffffu, rs1, 1);
    rs1 += __shfl_xor_sync(0xffffffffu, rs1, 2);

    int gq0 = qbase + w*16 + gid, gq1 = gq0 + 8;
    float* P0 = g_part + ((size_t)s*BD + gq0)*52;
    float* P1 = g_part + ((size_t)s*BD + gq1)*52;
    #pragma unroll
    for (int dt = 0; dt < 6; dt++) {
        int col = dt*8 + tg*2;
        P0[col]   = O[dt][0];
        P0[col+1] = O[dt][1];
        P1[col]   = O[dt][2];
        P1[col+1] = O[dt][3];
    }
    if (tg == 0) {
        P0[48] = rm0; P0[49] = rs0;
        P1[48] = rm1; P1[49] = rs1;
    }
}

// ---------- combine partials + emit pred + next q (8 q per block) ----------
__global__ void combine_kernel(const float* __restrict__ Wq, const float* __restrict__ bq,
                               int iter)
{
    __shared__ float sc[8][48];
    int t = threadIdx.x;
    int ql = t / 48, d = t - ql*48;
    int q = blockIdx.x*8 + ql;
    float gm = -1e30f;
    #pragma unroll 6
    for (int s = 0; s < NSLICE; s++)
        gm = fmaxf(gm, g_part[((size_t)s*BD+q)*52 + 48]);
    float tot = 0.f, av = 0.f;
    #pragma unroll 6
    for (int s = 0; s < NSLICE; s++) {
        const float* P = g_part + ((size_t)s*BD+q)*52;
        float e = __expf(P[48] - gm);
        tot = fmaf(P[49], e, tot);
        av  = fmaf(P[d],  e, av);
    }
    float att = av / tot;
    g_pred[(q*NPREDD + iter)*48 + d] = att;
    sc[ql][d] = g_q[q*48+d] + att;
    __syncthreads();
    float qn = bq[d];
    const float* w = Wq + d*48;
    #pragma unroll 8
    for (int k = 0; k < 48; k++) qn = fmaf(sc[ql][k], w[k], qn);
    g_q[q*48+d] = qn;
}

// ---------- decoder: register-resident HMMA GRU, 64 rows/CTA ----------
__device__ __forceinline__ float info_at(int n, int d){
    return (d < 48) ? g_state[(n/NPREDD)*48 + d] : g_pred[(size_t)n*48 + (d-48)];
}
__device__ __forceinline__ void stageW(unsigned* Wh32, unsigned* Wl32,
    const __nv_bfloat16* gh, const __nv_bfloat16* gl, int tid)
{
    const unsigned* sh = (const unsigned*)gh;
    const unsigned* sl = (const unsigned*)gl;
    for (int i = tid; i < 288*48; i += 128) {
        int j = i / 48, kk = i - j*48;
        int u = j*48 + (kk ^ (((j>>1)&3)*4));
        Wh32[u] = sh[i];
        Wl32[u] = sl[i];
    }
}

__global__ void __launch_bounds__(128,2) dec_kernel(
    const float* __restrict__ obs,
    const float* __restrict__ bih, const float* __restrict__ bhh,
    const float* __restrict__ fcw, const float* __restrict__ fcb,
    float* __restrict__ out)
{
    extern __shared__ char dsm[];
    unsigned* Wh32 = (unsigned*)dsm;
    unsigned* Wl32 = Wh32 + 288*48;
    float* sbrz = (float*)(dsm + DEC_W_BYTES);
    float* sbin = sbrz + 192;
    float* sbhn = sbin + 96;
    float* sfc  = sbhn + 96;

    int tid = threadIdx.x, lane = tid & 31, w = tid >> 5;
    int gid = lane >> 2, tg = lane & 3;
    int nbase = blockIdx.x*64;
    int r0 = nbase + w*16 + gid, r1 = r0 + 8;

    for (int i = tid; i < 192; i += 128) { sbrz[i] = bih[i] + bhh[i]; sfc[i] = fcw[i]; }
    for (int i = tid; i < 96; i += 128)  { sbin[i] = bih[192+i]; sbhn[i] = bhh[192+i]; }
    stageW(Wh32, Wl32, g_Wih_h, g_Wih_l, tid);

    unsigned ah[6][4], al[6][4];
    #pragma unroll
    for (int kt = 0; kt < 6; kt++) {
        int c = kt*16 + tg*2;
        split2(info_at(r0,c),   info_at(r0,c+1), ah[kt][0], al[kt][0]);
        split2(info_at(r1,c),   info_at(r1,c+1), ah[kt][1], al[kt][1]);
        split2(info_at(r0,c+8), info_at(r0,c+9), ah[kt][2], al[kt][2]);
        split2(info_at(r1,c+8), info_at(r1,c+9), ah[kt][3], al[kt][3]);
    }
    float pres00 = obs[(r0/NPREDD)*16 + 14], pres01 = obs[(r0/NPREDD)*16 + 15];
    float pres10 = obs[(r1/NPREDD)*16 + 14], pres11 = obs[(r1/NPREDD)*16 + 15];
    __syncthreads();

    for (int t = 0; t < FUTD; t++) {
        unsigned nh[6][4], nl[6][4];
        float f00 = 0.f, f01 = 0.f, f10 = 0.f, f11 = 0.f;

        #pragma unroll 1
        for (int g = 0; g < 12; g++) {
            float Cr[4] = {0,0,0,0}, Cz[4] = {0,0,0,0}, Cn[4] = {0,0,0,0};
            #pragma unroll
            for (int kt = 0; kt < 6; kt++) {
                unsigned a0 = ah[kt][0], a1 = ah[kt][1], a2 = ah[kt][2], a3 = ah[kt][3];
                unsigned b0 = al[kt][0], b1 = al[kt][1], b2x = al[kt][2], b3 = al[kt][3];
                #pragma unroll
                for (int gate = 0; gate < 3; gate++) {
                    int j = gate*96 + g*8 + gid;
                    int sw = ((j>>1)&3)*4;
                    int u0 = j*48 + ((kt*8+tg) ^ sw);
                    int u1 = j*48 + ((kt*8+4+tg) ^ sw);
                    unsigned bh0 = Wh32[u0], bh1 = Wh32[u1];
                    unsigned bl0 = Wl32[u0], bl1 = Wl32[u1];
                    float* C = (gate == 0) ? Cr : (gate == 1) ? Cz : Cn;
                    MMA_BF16(C, a0,a1,a2,a3, bh0,bh1);
                    MMA_BF16(C, a0,a1,a2,a3, bl0,bl1);
                    MMA_BF16(C, b0,b1,b2x,b3, bh0,bh1);
                }
            }
            int d0 = g*8 + tg*2;
            float brz0 = sbrz[d0],    brz1 = sbrz[d0+1];
            float bz0  = sbrz[96+d0], bz1  = sbrz[96+d0+1];
            float bin0 = sbin[d0],    bin1 = sbin[d0+1];
            float bhn0 = sbhn[d0],    bhn1 = sbhn[d0+1];
            float rg0 = sg_(Cr[0]+brz0), rg1 = sg_(Cr[1]+brz1);
            float rg2 = sg_(Cr[2]+brz0), rg3 = sg_(Cr[3]+brz1);
            float z0 = sg_(Cz[0]+bz0), z1 = sg_(Cz[1]+bz1);
            float z2 = sg_(Cz[2]+bz0), z3 = sg_(Cz[3]+bz1);
            float h0, h1, h2, h3;
            if (t == 0) {
                h0 = (1.f-z0)*tanhf(Cn[0] + bin0 + rg0*bhn0);
                h1 = (1.f-z1)*tanhf(Cn[1] + bin1 + rg1*bhn1);
                h2 = (1.f-z2)*tanhf(Cn[2] + bin0 + rg2*bhn0);
                h3 = (1.f-z3)*tanhf(Cn[3] + bin1 + rg3*bhn1);
            } else {
                int kt = g >> 1, s0 = (g & 1)*2;
                unsigned uh0 = ah[kt][s0],   ul0 = al[kt][s0];
                unsigned uh1 = ah[kt][s0+1], ul1 = al[kt][s0+1];
                float ho0 = bflo(uh0) + bflo(ul0), ho1 = bfhi(uh0) + bfhi(ul0);
                float ho2 = bflo(uh1) + bflo(ul1), ho3 = bfhi(uh1) + bfhi(ul1);
                h0 = (1.f-z0)*tanhf(bin0 + rg0*(Cn[0]+bhn0)) + z0*ho0;
                h1 = (1.f-z1)*tanhf(bin1 + rg1*(Cn[1]+bhn1)) + z1*ho1;
                h2 = (1.f-z2)*tanhf(bin0 + rg2*(Cn[2]+bhn0)) + z2*ho2;
                h3 = (1.f-z3)*tanhf(bin1 + rg3*(Cn[3]+bhn1)) + z3*ho3;
            }
            int kt2 = g >> 1, s0i = (g & 1)*2;
            split2(h0, h1, nh[kt2][s0i],   nl[kt2][s0i]);
            split2(h2, h3, nh[kt2][s0i+1], nl[kt2][s0i+1]);
            float w00 = sfc[d0], w01 = sfc[d0+1], w10 = sfc[96+d0], w11 = sfc[96+d0+1];
            f00 = fmaf(h0, w00, fmaf(h1, w01, f00));
            f01 = fmaf(h0, w10, fmaf(h1, w11, f01));
            f10 = fmaf(h2, w00, fmaf(h3, w01, f10));
            f11 = fmaf(h2, w10, fmaf(h3, w11, f11));
        }
        #pragma unroll
        for (int kt = 0; kt < 6; kt++)
            #pragma unroll
            for (int e = 0; e < 4; e++) { ah[kt][e] = nh[kt][e]; al[kt][e] = nl[kt][e]; }

        f00 += __shfl_xor_sync(0xffffffffu, f00, 1);
        f00 += __shfl_xor_sync(0xffffffffu, f00, 2);
        f01 += __shfl_xor_sync(0xffffffffu, f01, 1);
        f01 += __shfl_xor_sync(0xffffffffu, f01, 2);
        f10 += __shfl_xor_sync(0xffffffffu, f10, 1);
        f10 += __shfl_xor_sync(0xffffffffu, f10, 2);
        f11 += __shfl_xor_sync(0xffffffffu, f11, 1);
        f11 += __shfl_xor_sync(0xffffffffu, f11, 2);
        pres00 += f00 + fcb[0];
        pres01 += f01 + fcb[1];
        pres10 += f10 + fcb[0];
        pres11 += f11 + fcb[1];
        if (tg == 0) {
            out[((size_t)r0*FUTD + t)*2 + 0] = pres00;
            out[((size_t)r0*FUTD + t)*2 + 1] = pres01;
            out[((size_t)r1*FUTD + t)*2 + 0] = pres10;
            out[((size_t)r1*FUTD + t)*2 + 1] = pres11;
        }
        if (t == 0) {
            __syncthreads();
            stageW(Wh32, Wl32, g_Whh_h, g_Whh_l, tid);
            __syncthreads();
        }
    }
}

extern "C" void kernel_launch(void* const* d_in, const int* in_sizes, int n_in,
                              void* d_out, int out_size)
{
    const float* past    = (const float*)d_in[0];
    const float* obs     = (const float*)d_in[1];
    const float* conv_w  = (const float*)d_in[2];
    const float* conv_b  = (const float*)d_in[3];
    const float* enc_wih = (const float*)d_in[4];
    const float* enc_whh = (const float*)d_in[5];
    const float* enc_bih = (const float*)d_in[6];
    const float* enc_bhh = (const float*)d_in[7];
    const float* mem_p   = (const float*)d_in[8];
    const float* mem_f   = (const float*)d_in[9];
    const float* Wq      = (const float*)d_in[10];
    const float* bq      = (const float*)d_in[11];
    const float* Wk      = (const float*)d_in[12];
    const float* bk      = (const float*)d_in[13];
    const float* Wv      = (const float*)d_in[14];
    const float* bv      = (const float*)d_in[15];
    const float* dec_wih = (const float*)d_in[16];
    const float* dec_whh = (const float*)d_in[17];
    const float* dec_bih = (const float*)d_in[18];
    const float* dec_bhh = (const float*)d_in[19];
    const float* fc_w    = (const float*)d_in[20];
    const float* fc_b    = (const float*)d_in[21];
    float* out = (float*)d_out;

    cudaFuncSetAttribute(attn_kernel,
        cudaFuncAttributeMaxDynamicSharedMemorySize, SMEM_ATTN);
    cudaFuncSetAttribute(dec_kernel,
        cudaFuncAttributeMaxDynamicSharedMemorySize, DEC_SMEM);

    enc_kernel<<<BD, 144>>>(past, conv_w, conv_b, enc_wih, enc_whh,
                            enc_bih, enc_bhh, Wq, bq);
    kproj_kernel<<<(MD*48 + 255)/256, 256>>>(mem_p, Wk, bk);
    vproj_kernel<<<MD/256, 256>>>(mem_f, Wv, bv);
    wsplit_kernel<<<(288*96 + 255)/256, 256>>>(dec_wih, dec_whh);

    for (int it = 0; it < NPREDD; it++) {
        attn_kernel<<<dim3(NSLICE, BD/64), 128, SMEM_ATTN>>>();
        combine_kernel<<<64, 384>>>(Wq, bq, it);
    }

    dec_kernel<<<NROWS/64, 128, DEC_SMEM>>>(obs, dec_bih, dec_bhh, fc_w, fc_b, out);
}

// round 16
// speedup vs baseline: 1.5165x; 1.1061x over previous
#include <cuda_runtime.h>
#include <cuda_bf16.h>
#include <cuda_fp16.h>
#include <math.h>

#define BD 512
#define MD 32768
#define NPREDD 20
#define FUTD 12
#define NROWS (BD*NPREDD)
#define NSLICE 54

// attn smem: 2 KV buffers (K [64][56] half = 7168B, V [48][72] half = 6912B) + Q staging
#define KVBUF_B   14336
#define OFF_Q     (2*KVBUF_B)
#define SMEM_ATTN (OFF_Q + 64*48*4)

// decoder smem: W (hi+lo bf16) swizzled + small bias/fc tables
#define DEC_W_BYTES (288*96*2*2)
#define DEC_SMEM    (DEC_W_BYTES + 576*4)

__device__ float g_state[BD*48];
__device__ float g_q[BD*48];
__device__ __half g_K[MD*48];          // fp16 hi only
__device__ __half g_Vt[48*MD];         // fp16 hi only, d-major
__device__ float g_part[NSLICE*BD*52];
__device__ float g_pred[NROWS*48];
__device__ __nv_bfloat16 g_Wih_h[288*96];
__device__ __nv_bfloat16 g_Wih_l[288*96];
__device__ __nv_bfloat16 g_Whh_h[288*96];
__device__ __nv_bfloat16 g_Whh_l[288*96];

__device__ __forceinline__ float sg_(float x){ return 1.f/(1.f+__expf(-x)); }

__device__ __forceinline__ void cpa16(void* dst, const void* src){
    unsigned ds = (unsigned)__cvta_generic_to_shared(dst);
    asm volatile("cp.async.cg.shared.global [%0], [%1], 16;\n" :: "r"(ds), "l"(src));
}

#define MMA_BF16(c, a0,a1,a2,a3, b0,b1) \
    asm volatile("mma.sync.aligned.m16n8k16.row.col.f32.bf16.bf16.f32 " \
        "{%0,%1,%2,%3}, {%4,%5,%6,%7}, {%8,%9}, {%0,%1,%2,%3};" \
        : "+f"(c[0]), "+f"(c[1]), "+f"(c[2]), "+f"(c[3]) \
        : "r"(a0),"r"(a1),"r"(a2),"r"(a3),"r"(b0),"r"(b1))

#define MMA_F16(c, a0,a1,a2,a3, b0,b1) \
    asm volatile("mma.sync.aligned.m16n8k16.row.col.f32.f16.f16.f32 " \
        "{%0,%1,%2,%3}, {%4,%5,%6,%7}, {%8,%9}, {%0,%1,%2,%3};" \
        : "+f"(c[0]), "+f"(c[1]), "+f"(c[2]), "+f"(c[3]) \
        : "r"(a0),"r"(a1),"r"(a2),"r"(a3),"r"(b0),"r"(b1))

__device__ __forceinline__ unsigned ldu32(const __nv_bfloat16* p){ return *(const unsigned*)p; }
__device__ __forceinline__ unsigned ldu32h(const __half* p){ return *(const unsigned*)p; }
__device__ __forceinline__ unsigned short us_(__nv_bfloat16 h){ return *(unsigned short*)&h; }
__device__ __forceinline__ unsigned short ush_(__half h){ return *(unsigned short*)&h; }

// bf16 hi/lo split (decoder path)
__device__ __forceinline__ void split2(float a, float b, unsigned &hi, unsigned &lo){
    __nv_bfloat16 ha = __float2bfloat16(a), hb = __float2bfloat16(b);
    __nv_bfloat16 la = __float2bfloat16(a - __bfloat162float(ha));
    __nv_bfloat16 lb = __float2bfloat16(b - __bfloat162float(hb));
    hi = (unsigned)us_(ha) | ((unsigned)us_(hb) << 16);
    lo = (unsigned)us_(la) | ((unsigned)us_(lb) << 16);
}
__device__ __forceinline__ void splits(float v, __nv_bfloat16* ph, __nv_bfloat16* pl){
    __nv_bfloat16 h = __float2bfloat16(v);
    *ph = h;
    *pl = __float2bfloat16(v - __bfloat162float(h));
}
// fp16 hi/lo split (attention Q path)
__device__ __forceinline__ void split2h(float a, float b, unsigned &hi, unsigned &lo){
    __half ha = __float2half_rn(a), hb = __float2half_rn(b);
    __half la = __float2half_rn(a - __half2float(ha));
    __half lb = __float2half_rn(b - __half2float(hb));
    hi = (unsigned)ush_(ha) | ((unsigned)ush_(hb) << 16);
    lo = (unsigned)ush_(la) | ((unsigned)ush_(lb) << 16);
}
// fp16 pack only (attention P path — no residual)
__device__ __forceinline__ unsigned pack2h(float a, float b){
    __half2 h2 = __floats2half2_rn(a, b);
    return *(unsigned*)&h2;
}
__device__ __forceinline__ float bflo(unsigned u){
    return __bfloat162float(__ushort_as_bfloat16((unsigned short)(u & 0xffffu)));
}
__device__ __forceinline__ float bfhi(unsigned u){
    return __bfloat162float(__ushort_as_bfloat16((unsigned short)(u >> 16)));
}

// ---------- encoder ----------
__global__ void enc_kernel(const float* __restrict__ past,
    const float* __restrict__ cw, const float* __restrict__ cb,
    const float* __restrict__ wih, const float* __restrict__ whh,
    const float* __restrict__ bih, const float* __restrict__ bhh,
    const float* __restrict__ Wq, const float* __restrict__ bq)
{
    __shared__ float se[8][48];
    __shared__ float sh[48];
    __shared__ float sgi[144], sgh[144];
    int b = blockIdx.x, tid = threadIdx.x;
    for (int idx = tid; idx < 8*48; idx += 144) {
        int t = idx/48, c = idx%48;
        float s = cb[c];
        #pragma unroll
        for (int k = 0; k < 3; k++) {
            int tt = t + k - 1;
            if (tt >= 0 && tt < 8) {
                s = fmaf(cw[c*6+k],   past[b*16+tt*2+0], s);
                s = fmaf(cw[c*6+3+k], past[b*16+tt*2+1], s);
            }
        }
        se[t][c] = fmaxf(s, 0.f);
    }
    if (tid < 48) sh[tid] = 0.f;
    __syncthreads();
    for (int t = 0; t < 8; t++) {
        float gi = bih[tid], gh = bhh[tid];
        const float* wi = wih + tid*48;
        const float* wh = whh + tid*48;
        #pragma unroll 8
        for (int d = 0; d < 48; d++) {
            gi = fmaf(se[t][d], wi[d], gi);
            gh = fmaf(sh[d],    wh[d], gh);
        }
        sgi[tid] = gi; sgh[tid] = gh;
        __syncthreads();
        float hn = 0.f;
        if (tid < 48) {
            float r = sg_(sgi[tid]    + sgh[tid]);
            float z = sg_(sgi[48+tid] + sgh[48+tid]);
            float n = tanhf(sgi[96+tid] + r*sgh[96+tid]);
            hn = (1.f-z)*n + z*sh[tid];
        }
        __syncthreads();
        if (tid < 48) sh[tid] = hn;
        __syncthreads();
    }
    if (tid < 48) {
        g_state[b*48+tid] = sh[tid];
        float q = bq[tid];
        const float* w = Wq + tid*48;
        #pragma unroll 8
        for (int d = 0; d < 48; d++) q = fmaf(sh[d], w[d], q);
        g_q[b*48+tid] = q;
    }
}

// ---------- K projection (fp16 hi only, m-major) ----------
__global__ void kproj_kernel(const float* __restrict__ mp,
    const float* __restrict__ Wk, const float* __restrict__ bk)
{
    int idx = blockIdx.x*blockDim.x + threadIdx.x;
    if (idx >= MD*48) return;
    int m = idx/48, j = idx - m*48;
    const float* rp = mp + m*48;
    const float* wk = Wk + j*48;
    float sk = bk[j];
    #pragma unroll 8
    for (int d = 0; d < 48; d++) sk = fmaf(rp[d], wk[d], sk);
    g_K[idx] = __float2half_rn(sk);
}

// ---------- V projection (fp16 hi only, transposed d-major) ----------
__global__ void vproj_kernel(const float* __restrict__ mf,
    const float* __restrict__ Wv, const float* __restrict__ bv)
{
    __shared__ float sW[48*48];
    __shared__ float sb[48];
    int tid = threadIdx.x;
    for (int i = tid; i < 48*48; i += 256) sW[i] = Wv[i];
    if (tid < 48) sb[tid] = bv[tid];
    __syncthreads();
    int m = blockIdx.x*256 + tid;
    float r[48];
    #pragma unroll 8
    for (int d = 0; d < 48; d++) r[d] = mf[(size_t)m*48 + d];
    #pragma unroll 1
    for (int j = 0; j < 48; j++) {
        float sv = sb[j];
        const float* w = sW + j*48;
        #pragma unroll 8
        for (int d = 0; d < 48; d++) sv = fmaf(r[d], w[d], sv);
        g_Vt[(size_t)j*MD + m] = __float2half_rn(sv);
    }
}

// ---------- decoder weight hi/lo split (bf16) ----------
__global__ void wsplit_kernel(const float* __restrict__ wih, const float* __restrict__ whh)
{
    int i = blockIdx.x*blockDim.x + threadIdx.x;
    if (i < 288*96) {
        splits(wih[i], &g_Wih_h[i], &g_Wih_l[i]);
        splits(whh[i], &g_Whh_h[i], &g_Whh_l[i]);
    }
}

// ---------- prefetch helper (attn): K rows 96B, V rows 128B ----------
__device__ __forceinline__ void prefetch_chunk(char* base, int m0, int tid){
    #pragma unroll
    for (int i = tid; i < 384; i += 128) {
        int r = i/6, seg = i - (i/6)*6;
        cpa16(base + r*112 + seg*16,
              (const char*)g_K + (size_t)(m0+r)*96 + seg*16);
    }
    #pragma unroll
    for (int i = tid; i < 384; i += 128) {
        int r = i >> 3, seg = i & 7;
        cpa16(base + 7168 + r*144 + seg*16,
              (const char*)g_Vt + ((size_t)r*MD + m0)*2 + seg*16);
    }
}

// ---------- attention: register-resident FA2, fp16 HMMA, P hi-only PV ----------
__global__ void __launch_bounds__(128,3) attn_kernel()
{
    extern __shared__ char sm[];
    int tid = threadIdx.x, lane = tid & 31, w = tid >> 5;
    int gid = lane >> 2, tg = lane & 3;
    int qbase = blockIdx.y * 64;
    int s = blockIdx.x;
    int m_start = (s < 26) ? s*640 : 16640 + (s-26)*576;
    int nch = (s < 26) ? 10 : 9;

    float* sQ = (float*)(sm + OFF_Q);
    for (int i = tid; i < 64*48; i += 128) sQ[i] = g_q[qbase*48 + i];
    __syncthreads();

    unsigned qh[3][4], ql[3][4];
    {
        int r0 = w*16 + gid, r1 = r0 + 8;
        #pragma unroll
        for (int j = 0; j < 3; j++) {
            int c = j*16 + tg*2;
            split2h(sQ[r0*48 + c],     sQ[r0*48 + c + 1],     qh[j][0], ql[j][0]);
            split2h(sQ[r1*48 + c],     sQ[r1*48 + c + 1],     qh[j][1], ql[j][1]);
            split2h(sQ[r0*48 + c + 8], sQ[r0*48 + c + 9],     qh[j][2], ql[j][2]);
            split2h(sQ[r1*48 + c + 8], sQ[r1*48 + c + 9],     qh[j][3], ql[j][3]);
        }
    }

    prefetch_chunk(sm, m_start, tid);
    asm volatile("cp.async.commit_group;\n");

    float O[6][4];
    #pragma unroll
    for (int dt = 0; dt < 6; dt++) { O[dt][0]=0.f; O[dt][1]=0.f; O[dt][2]=0.f; O[dt][3]=0.f; }
    float rm0 = -1e30f, rm1 = -1e30f, rs0 = 0.f, rs1 = 0.f;

    for (int c = 0; c < nch; c++) {
        asm volatile("cp.async.wait_group 0;\n" ::: "memory");
        __syncthreads();
        if (c + 1 < nch)
            prefetch_chunk(sm + ((c+1)&1)*KVBUF_B, m_start + (c+1)*64, tid);
        asm volatile("cp.async.commit_group;\n");

        const __half* K = (const __half*)(sm + (c&1)*KVBUF_B);
        const __half* V = (const __half*)(sm + (c&1)*KVBUF_B + 7168);

        // ---- QK^T: 2 MMAs per tile (qh·k, ql·k) ----
        float Sc[8][4];
        #pragma unroll
        for (int nt = 0; nt < 8; nt++) { Sc[nt][0]=0.f; Sc[nt][1]=0.f; Sc[nt][2]=0.f; Sc[nt][3]=0.f; }
        #pragma unroll
        for (int j = 0; j < 3; j++) {
            int kc = j*16 + tg*2;
            #pragma unroll
            for (int nt = 0; nt < 8; nt++) {
                const __half* kr = K + (nt*8+gid)*56 + kc;
                unsigned k0 = ldu32h(kr), k1 = ldu32h(kr + 8);
                MMA_F16(Sc[nt], qh[j][0],qh[j][1],qh[j][2],qh[j][3], k0,k1);
                MMA_F16(Sc[nt], ql[j][0],ql[j][1],ql[j][2],ql[j][3], k0,k1);
            }
        }

        // ---- online softmax (row = 4 lanes of a quad) ----
        float m0 = Sc[0][0], m1 = Sc[0][2];
        #pragma unroll
        for (int nt = 0; nt < 8; nt++) {
            m0 = fmaxf(m0, fmaxf(Sc[nt][0], Sc[nt][1]));
            m1 = fmaxf(m1, fmaxf(Sc[nt][2], Sc[nt][3]));
        }
        m0 = fmaxf(m0, __shfl_xor_sync(0xffffffffu, m0, 1));
        m0 = fmaxf(m0, __shfl_xor_sync(0xffffffffu, m0, 2));
        m1 = fmaxf(m1, __shfl_xor_sync(0xffffffffu, m1, 1));
        m1 = fmaxf(m1, __shfl_xor_sync(0xffffffffu, m1, 2));
        float nm0 = fmaxf(rm0, m0), nm1 = fmaxf(rm1, m1);
        float f0 = __expf(rm0 - nm0), f1 = __expf(rm1 - nm1);
        rm0 = nm0; rm1 = nm1;
        rs0 *= f0; rs1 *= f1;
        #pragma unroll
        for (int dt = 0; dt < 6; dt++) {
            O[dt][0] *= f0; O[dt][1] *= f0;
            O[dt][2] *= f1; O[dt][3] *= f1;
        }

        // ---- exp + PV: P rounded to single fp16 (1 MMA per tile) ----
        unsigned p01[8], p23[8];
        #pragma unroll
        for (int nt = 0; nt < 8; nt++) {
            float p0 = __expf(Sc[nt][0] - nm0);
            float p1 = __expf(Sc[nt][1] - nm0);
            float p2 = __expf(Sc[nt][2] - nm1);
            float p3 = __expf(Sc[nt][3] - nm1);
            rs0 += p0 + p1; rs1 += p2 + p3;
            p01[nt] = pack2h(p0, p1);
            p23[nt] = pack2h(p2, p3);
        }
        #pragma unroll
        for (int t = 0; t < 4; t++) {
            unsigned a0 = p01[2*t],   a1 = p23[2*t];
            unsigned a2 = p01[2*t+1], a3 = p23[2*t+1];
            int mk = t*16 + tg*2;
            #pragma unroll
            for (int dt = 0; dt < 6; dt++) {
                const __half* vr = V + (dt*8+gid)*72 + mk;
                unsigned v0 = ldu32h(vr), v1 = ldu32h(vr + 8);
                MMA_F16(O[dt], a0,a1,a2,a3, v0,v1);
            }
        }
    }

    rs0 += __shfl_xor_sync(0xffffffffu, rs0, 1);
    rs0 += __shfl_xor_sync(0xffffffffu, rs0, 2);
    rs1 += __shfl_xor_sync(0xffffffffu, rs1, 1);
    rs1 += __shfl_xor_sync(0xffffffffu, rs1, 2);

    int gq0 = qbase + w*16 + gid, gq1 = gq0 + 8;
    float* P0 = g_part + ((size_t)s*BD + gq0)*52;
    float* P1 = g_part + ((size_t)s*BD + gq1)*52;
    #pragma unroll
    for (int dt = 0; dt < 6; dt++) {
        int col = dt*8 + tg*2;
        P0[col]   = O[dt][0];
        P0[col+1] = O[dt][1];
        P1[col]   = O[dt][2];
        P1[col+1] = O[dt][3];
    }
    if (tg == 0) {
        P0[48] = rm0; P0[49] = rs0;
        P1[48] = rm1; P1[49] = rs1;
    }
}

// ---------- combine partials + emit pred + next q (8 q per block) ----------
__global__ void combine_kernel(const float* __restrict__ Wq, const float* __restrict__ bq,
                               int iter)
{
    __shared__ float sc[8][48];
    int t = threadIdx.x;
    int ql = t / 48, d = t - ql*48;
    int q = blockIdx.x*8 + ql;
    float gm = -1e30f;
    #pragma unroll 6
    for (int s = 0; s < NSLICE; s++)
        gm = fmaxf(gm, g_part[((size_t)s*BD+q)*52 + 48]);
    float tot = 0.f, av = 0.f;
    #pragma unroll 6
    for (int s = 0; s < NSLICE; s++) {
        const float* P = g_part + ((size_t)s*BD+q)*52;
        float e = __expf(P[48] - gm);
        tot = fmaf(P[49], e, tot);
        av  = fmaf(P[d],  e, av);
    }
    float att = av / tot;
    g_pred[(q*NPREDD + iter)*48 + d] = att;
    sc[ql][d] = g_q[q*48+d] + att;
    __syncthreads();
    float qn = bq[d];
    const float* w = Wq + d*48;
    #pragma unroll 8
    for (int k = 0; k < 48; k++) qn = fmaf(sc[ql][k], w[k], qn);
    g_q[q*48+d] = qn;
}

// ---------- decoder: register-resident HMMA GRU, 64 rows/CTA ----------
__device__ __forceinline__ float info_at(int n, int d){
    return (d < 48) ? g_state[(n/NPREDD)*48 + d] : g_pred[(size_t)n*48 + (d-48)];
}
__device__ __forceinline__ void stageW(unsigned* Wh32, unsigned* Wl32,
    const __nv_bfloat16* gh, const __nv_bfloat16* gl, int tid)
{
    const unsigned* sh = (const unsigned*)gh;
    const unsigned* sl = (const unsigned*)gl;
    for (int i = tid; i < 288*48; i += 128) {
        int j = i / 48, kk = i - j*48;
        int u = j*48 + (kk ^ (((j>>1)&3)*4));
        Wh32[u] = sh[i];
        Wl32[u] = sl[i];
    }
}

__global__ void __launch_bounds__(128,2) dec_kernel(
    const float* __restrict__ obs,
    const float* __restrict__ bih, const float* __restrict__ bhh,
    const float* __restrict__ fcw, const float* __restrict__ fcb,
    float* __restrict__ out)
{
    extern __shared__ char dsm[];
    unsigned* Wh32 = (unsigned*)dsm;
    unsigned* Wl32 = Wh32 + 288*48;
    float* sbrz = (float*)(dsm + DEC_W_BYTES);
    float* sbin = sbrz + 192;
    float* sbhn = sbin + 96;
    float* sfc  = sbhn + 96;

    int tid = threadIdx.x, lane = tid & 31, w = tid >> 5;
    int gid = lane >> 2, tg = lane & 3;
    int nbase = blockIdx.x*64;
    int r0 = nbase + w*16 + gid, r1 = r0 + 8;

    for (int i = tid; i < 192; i += 128) { sbrz[i] = bih[i] + bhh[i]; sfc[i] = fcw[i]; }
    for (int i = tid; i < 96; i += 128)  { sbin[i] = bih[192+i]; sbhn[i] = bhh[192+i]; }
    stageW(Wh32, Wl32, g_Wih_h, g_Wih_l, tid);

    unsigned ah[6][4], al[6][4];
    #pragma unroll
    for (int kt = 0; kt < 6; kt++) {
        int c = kt*16 + tg*2;
        split2(info_at(r0,c),   info_at(r0,c+1), ah[kt][0], al[kt][0]);
        split2(info_at(r1,c),   info_at(r1,c+1), ah[kt][1], al[kt][1]);
        split2(info_at(r0,c+8), info_at(r0,c+9), ah[kt][2], al[kt][2]);
        split2(info_at(r1,c+8), info_at(r1,c+9), ah[kt][3], al[kt][3]);
    }
    float pres00 = obs[(r0/NPREDD)*16 + 14], pres01 = obs[(r0/NPREDD)*16 + 15];
    float pres10 = obs[(r1/NPREDD)*16 + 14], pres11 = obs[(r1/NPREDD)*16 + 15];
    __syncthreads();

    for (int t = 0; t < FUTD; t++) {
        unsigned nh[6][4], nl[6][4];
        float f00 = 0.f, f01 = 0.f, f10 = 0.f, f11 = 0.f;

        #pragma unroll 1
        for (int g = 0; g < 12; g++) {
            float Cr[4] = {0,0,0,0}, Cz[4] = {0,0,0,0}, Cn[4] = {0,0,0,0};
            #pragma unroll
            for (int kt = 0; kt < 6; kt++) {
                unsigned a0 = ah[kt][0], a1 = ah[kt][1], a2 = ah[kt][2], a3 = ah[kt][3];
                unsigned b0 = al[kt][0], b1 = al[kt][1], b2x = al[kt][2], b3 = al[kt][3];
                #pragma unroll
                for (int gate = 0; gate < 3; gate++) {
                    int j = gate*96 + g*8 + gid;
                    int sw = ((j>>1)&3)*4;
                    int u0 = j*48 + ((kt*8+tg) ^ sw);
                    int u1 = j*48 + ((kt*8+4+tg) ^ sw);
                    unsigned bh0 = Wh32[u0], bh1 = Wh32[u1];
                    unsigned bl0 = Wl32[u0], bl1 = Wl32[u1];
                    float* C = (gate == 0) ? Cr : (gate == 1) ? Cz : Cn;
                    MMA_BF16(C, a0,a1,a2,a3, bh0,bh1);
                    MMA_BF16(C, a0,a1,a2,a3, bl0,bl1);
                    MMA_BF16(C, b0,b1,b2x,b3, bh0,bh1);
                }
            }
            int d0 = g*8 + tg*2;
            float brz0 = sbrz[d0],    brz1 = sbrz[d0+1];
            float bz0  = sbrz[96+d0], bz1  = sbrz[96+d0+1];
            float bin0 = sbin[d0],    bin1 = sbin[d0+1];
            float bhn0 = sbhn[d0],    bhn1 = sbhn[d0+1];
            float rg0 = sg_(Cr[0]+brz0), rg1 = sg_(Cr[1]+brz1);
            float rg2 = sg_(Cr[2]+brz0), rg3 = sg_(Cr[3]+brz1);
            float z0 = sg_(Cz[0]+bz0), z1 = sg_(Cz[1]+bz1);
            float z2 = sg_(Cz[2]+bz0), z3 = sg_(Cz[3]+bz1);
            float h0, h1, h2, h3;
            if (t == 0) {
                h0 = (1.f-z0)*tanhf(Cn[0] + bin0 + rg0*bhn0);
                h1 = (1.f-z1)*tanhf(Cn[1] + bin1 + rg1*bhn1);
                h2 = (1.f-z2)*tanhf(Cn[2] + bin0 + rg2*bhn0);
                h3 = (1.f-z3)*tanhf(Cn[3] + bin1 + rg3*bhn1);
            } else {
                int kt = g >> 1, s0 = (g & 1)*2;
                unsigned uh0 = ah[kt][s0],   ul0 = al[kt][s0];
                unsigned uh1 = ah[kt][s0+1], ul1 = al[kt][s0+1];
                float ho0 = bflo(uh0) + bflo(ul0), ho1 = bfhi(uh0) + bfhi(ul0);
                float ho2 = bflo(uh1) + bflo(ul1), ho3 = bfhi(uh1) + bfhi(ul1);
                h0 = (1.f-z0)*tanhf(bin0 + rg0*(Cn[0]+bhn0)) + z0*ho0;
                h1 = (1.f-z1)*tanhf(bin1 + rg1*(Cn[1]+bhn1)) + z1*ho1;
                h2 = (1.f-z2)*tanhf(bin0 + rg2*(Cn[2]+bhn0)) + z2*ho2;
                h3 = (1.f-z3)*tanhf(bin1 + rg3*(Cn[3]+bhn1)) + z3*ho3;
            }
            int kt2 = g >> 1, s0i = (g & 1)*2;
            split2(h0, h1, nh[kt2][s0i],   nl[kt2][s0i]);
            split2(h2, h3, nh[kt2][s0i+1], nl[kt2][s0i+1]);
            float w00 = sfc[d0], w01 = sfc[d0+1], w10 = sfc[96+d0], w11 = sfc[96+d0+1];
            f00 = fmaf(h0, w00, fmaf(h1, w01, f00));
            f01 = fmaf(h0, w10, fmaf(h1, w11, f01));
            f10 = fmaf(h2, w00, fmaf(h3, w01, f10));
            f11 = fmaf(h2, w10, fmaf(h3, w11, f11));
        }
        #pragma unroll
        for (int kt = 0; kt < 6; kt++)
            #pragma unroll
            for (int e = 0; e < 4; e++) { ah[kt][e] = nh[kt][e]; al[kt][e] = nl[kt][e]; }

        f00 += __shfl_xor_sync(0xffffffffu, f00, 1);
        f00 += __shfl_xor_sync(0xffffffffu, f00, 2);
        f01 += __shfl_xor_sync(0xffffffffu, f01, 1);
        f01 += __shfl_xor_sync(0xffffffffu, f01, 2);
        f10 += __shfl_xor_sync(0xffffffffu, f10, 1);
        f10 += __shfl_xor_sync(0xffffffffu, f10, 2);
        f11 += __shfl_xor_sync(0xffffffffu, f11, 1);
        f11 += __shfl_xor_sync(0xffffffffu, f11, 2);
        pres00 += f00 + fcb[0];
        pres01 += f01 + fcb[1];
        pres10 += f10 + fcb[0];
        pres11 += f11 + fcb[1];
        if (tg == 0) {
            out[((size_t)r0*FUTD + t)*2 + 0] = pres00;
            out[((size_t)r0*FUTD + t)*2 + 1] = pres01;
            out[((size_t)r1*FUTD + t)*2 + 0] = pres10;
            out[((size_t)r1*FUTD + t)*2 + 1] = pres11;
        }
        if (t == 0) {
            __syncthreads();
            stageW(Wh32, Wl32, g_Whh_h, g_Whh_l, tid);
            __syncthreads();
        }
    }
}

extern "C" void kernel_launch(void* const* d_in, const int* in_sizes, int n_in,
                              void* d_out, int out_size)
{
    const float* past    = (const float*)d_in[0];
    const float* obs     = (const float*)d_in[1];
    const float* conv_w  = (const float*)d_in[2];
    const float* conv_b  = (const float*)d_in[3];
    const float* enc_wih = (const float*)d_in[4];
    const float* enc_whh = (const float*)d_in[5];
    const float* enc_bih = (const float*)d_in[6];
    const float* enc_bhh = (const float*)d_in[7];
    const float* mem_p   = (const float*)d_in[8];
    const float* mem_f   = (const float*)d_in[9];
    const float* Wq      = (const float*)d_in[10];
    const float* bq      = (const float*)d_in[11];
    const float* Wk      = (const float*)d_in[12];
    const float* bk      = (const float*)d_in[13];
    const float* Wv      = (const float*)d_in[14];
    const float* bv      = (const float*)d_in[15];
    const float* dec_wih = (const float*)d_in[16];
    const float* dec_whh = (const float*)d_in[17];
    const float* dec_bih = (const float*)d_in[18];
    const float* dec_bhh = (const float*)d_in[19];
    const float* fc_w    = (const float*)d_in[20];
    const float* fc_b    = (const float*)d_in[21];
    float* out = (float*)d_out;

    cudaFuncSetAttribute(attn_kernel,
        cudaFuncAttributeMaxDynamicSharedMemorySize, SMEM_ATTN);
    cudaFuncSetAttribute(dec_kernel,
        cudaFuncAttributeMaxDynamicSharedMemorySize, DEC_SMEM);

    enc_kernel<<<BD, 144>>>(past, conv_w, conv_b, enc_wih, enc_whh,
                            enc_bih, enc_bhh, Wq, bq);
    kproj_kernel<<<(MD*48 + 255)/256, 256>>>(mem_p, Wk, bk);
    vproj_kernel<<<MD/256, 256>>>(mem_f, Wv, bv);
    wsplit_kernel<<<(288*96 + 255)/256, 256>>>(dec_wih, dec_whh);

    for (int it = 0; it < NPREDD; it++) {
        attn_kernel<<<dim3(NSLICE, BD/64), 128, SMEM_ATTN>>>();
        combine_kernel<<<64, 384>>>(Wq, bq, it);
    }

    dec_kernel<<<NROWS/64, 128, DEC_SMEM>>>(obs, dec_bih, dec_bhh, fc_w, fc_b, out);
}